// round 11
// baseline (speedup 1.0000x reference)
#include <cuda_runtime.h>
#include <cstddef>

// ---------------------------------------------------------------------------
// StackSAModuleMSG — tf32 tensor cores; gemm2 N-split for 2 CTAs/SM.
// B=4, NB=8192, MB=2048, M=8192, C_IN=64, CIN=67 (K padded to 72).
// Scale 0: r=0.2, NS=16 (R=131072).  Scale 1: r=0.4, NS=32 (R=262144).
//
// Launches (5): ballquery(+zero stats+copy new_xyz)
//   -> gemm1_merged (gather fused, stats fused; both scales)
//   -> gemm2_tc<32> (scale 1 first: X0b tail L2-hot)
//   -> gemm2_tc<16>
//   -> poolout (BN finalize inline on pooled raw values)
// X1 never touches DRAM: per-query raw max/min pooled in gemm2 registers.
// max_j relu(bn(x)) == relu(bn(max_j x)) for s>=0 (min for s<0): monotone.
// ---------------------------------------------------------------------------

#define MTOT 8192
#define NPB  8192

__device__ float g_X0a[131072 * 128];
__device__ float g_X0b[262144 * 128];
__device__ int   g_idx0[8192 * 16];
__device__ int   g_idx1[8192 * 32];
__device__ float g_mx0[8192 * 128];
__device__ float g_mn0[8192 * 128];
__device__ float g_mx1[8192 * 128];
__device__ float g_mn1[8192 * 128];
__device__ float g_sumA[512];   // slots: 0=g1/s0, 1=g2/s0, 2=g1/s1, 3=g2/s1
__device__ float g_sqA[512];

__device__ __forceinline__ unsigned f2tf(float f) {
    unsigned r;
    asm("cvt.rna.tf32.f32 %0, %1;" : "=r"(r) : "f"(f));
    return r;
}

__device__ __forceinline__ void mma_tf32(float* c, unsigned a0, unsigned a1,
                                         unsigned a2, unsigned a3, unsigned b0,
                                         unsigned b1) {
    asm volatile(
        "mma.sync.aligned.m16n8k8.row.col.f32.tf32.tf32.f32 "
        "{%0,%1,%2,%3}, {%4,%5,%6,%7}, {%8,%9}, {%0,%1,%2,%3};"
        : "+f"(c[0]), "+f"(c[1]), "+f"(c[2]), "+f"(c[3])
        : "r"(a0), "r"(a1), "r"(a2), "r"(a3), "r"(b0), "r"(b1));
}

// ---------------------------------------------------------------------------
// Merged ball query: warp per query, both scales. Exact fp32 arithmetic.
// Folds stats zeroing and the new_xyz -> output-head copy.
// ---------------------------------------------------------------------------
__global__ void ballquery_merged(const float* __restrict__ xyz,
                                 const float* __restrict__ newxyz,
                                 float r2_0, float r2_1,
                                 const float* __restrict__ copySrc,
                                 float* __restrict__ copyDst, int copyN) {
    int tid = threadIdx.x;
    if (blockIdx.x == 0) {
        g_sumA[tid] = 0.0f; g_sumA[tid + 256] = 0.0f;
        g_sqA[tid]  = 0.0f; g_sqA[tid + 256]  = 0.0f;
    }
    int ct = blockIdx.x * 256 + tid;
    if (ct < copyN) copyDst[ct] = copySrc[ct];

    int gw   = (blockIdx.x * 256 + tid) >> 5;
    int lane = tid & 31;
    if (gw >= 2 * MTOT) return;
    int scl = gw >> 13;
    int q   = gw & (MTOT - 1);
    int NS  = scl ? 32 : 16;
    float r2 = scl ? r2_1 : r2_0;
    int* idx_out = (scl ? g_idx1 : g_idx0) + q * NS;

    int b = q >> 11;
    float qx = newxyz[q * 3 + 0];
    float qy = newxyz[q * 3 + 1];
    float qz = newxyz[q * 3 + 2];
    float qq = __fadd_rn(__fadd_rn(__fmul_rn(qx, qx), __fmul_rn(qy, qy)),
                         __fmul_rn(qz, qz));
    const float* P = xyz + (size_t)b * NPB * 3;
    int cnt = 0, first = -1;
    for (int start = 0; start < NPB; start += 32) {
        int i = start + lane;
        float px = P[i * 3 + 0];
        float py = P[i * 3 + 1];
        float pz = P[i * 3 + 2];
        float pp = __fadd_rn(__fadd_rn(__fmul_rn(px, px), __fmul_rn(py, py)),
                             __fmul_rn(pz, pz));
        float dt = __fadd_rn(__fadd_rn(__fmul_rn(qx, px), __fmul_rn(qy, py)),
                             __fmul_rn(qz, pz));
        float d2 = __fsub_rn(__fadd_rn(qq, pp), __fmul_rn(2.0f, dt));
        bool in = d2 < r2;
        unsigned mask = __ballot_sync(0xFFFFFFFFu, in);
        if (mask) {
            if (first < 0) first = start + (__ffs(mask) - 1);
            int pos = cnt + __popc(mask & ((1u << lane) - 1u));
            if (in && pos < NS) idx_out[pos] = i;
            cnt += __popc(mask);
            if (cnt >= NS) break;
        }
    }
    if (cnt == 0) {
        for (int j = lane; j < NS; j += 32) idx_out[j] = -1;
    } else if (cnt < NS) {
        for (int j = cnt + lane; j < NS; j += 32) idx_out[j] = first;
    }
}

// ---------------------------------------------------------------------------
// GEMM1 merged: X0[R,128] = gather(G)[R,67] @ W0^T, both scales.
// 512 threads, 16 warps (4m x 4n), warp tile 32x32, block 128x128.
// Smem pitch 76 (conflict-free frag loads). Stats fused in epilogue.
// ---------------------------------------------------------------------------
#define PA1 76
#define KP1 72
#define KS1 9
#define SMEM1B ((128 * PA1 * 2 + 256) * 4)

__global__ __launch_bounds__(512, 2) void gemm1_merged(
    const float* __restrict__ xyz, const float* __restrict__ feat,
    const float* __restrict__ newxyz, const float* __restrict__ w00,
    const float* __restrict__ w10) {
    extern __shared__ unsigned sh[];
    unsigned* As = sh;              // [128][76]
    unsigned* Ws = sh + 128 * PA1;  // [128][76]  (W[o][c])
    float* s_sum = (float*)(sh + 2 * 128 * PA1);
    float* s_sq  = s_sum + 128;
    int tid = threadIdx.x;
    int bid = blockIdx.x;
    int scl = bid >= 1024;
    int lb  = scl ? bid - 1024 : bid;
    int nsShift = scl ? 5 : 4;
    const int* idx = scl ? g_idx1 : g_idx0;
    const float* w0 = scl ? w10 : w00;
    float* X0 = scl ? g_X0b : g_X0a;
    float* sum_out = g_sumA + (scl ? 256 : 0);
    float* sq_out  = g_sqA + (scl ? 256 : 0);

    if (tid < 128) { s_sum[tid] = 0.0f; s_sq[tid] = 0.0f; }
    for (int i = tid; i < 128 * KP1; i += 512) {
        int o = i / KP1;
        int c = i - o * KP1;
        Ws[o * PA1 + c] = (c < 67) ? f2tf(w0[o * 67 + c]) : 0u;
    }

    int row0 = lb * 128;
    {
        int r = tid >> 2, lw = tid & 3;
        int rg = row0 + r;
        int m  = rg >> nsShift;
        int p  = idx[rg];
        unsigned* grow = As + r * PA1;
        if (p < 0) {
#pragma unroll
            for (int c = lw * 18; c < lw * 18 + 18; ++c) grow[c] = 0u;
        } else {
            int gp = ((m >> 11) << 13) + p;
            if (lw == 0) {
                grow[0] = f2tf(xyz[gp * 3 + 0] - newxyz[m * 3 + 0]);
                grow[1] = f2tf(xyz[gp * 3 + 1] - newxyz[m * 3 + 1]);
                grow[2] = f2tf(xyz[gp * 3 + 2] - newxyz[m * 3 + 2]);
            }
            const float4* frow = (const float4*)(feat + (size_t)gp * 64);
#pragma unroll
            for (int j = 0; j < 4; ++j) {
                int f = lw + 4 * j;
                float4 v = frow[f];
                grow[3 + 4 * f + 0] = f2tf(v.x);
                grow[3 + 4 * f + 1] = f2tf(v.y);
                grow[3 + 4 * f + 2] = f2tf(v.z);
                grow[3 + 4 * f + 3] = f2tf(v.w);
            }
            if (lw == 3) {
                grow[67] = 0u; grow[68] = 0u; grow[69] = 0u;
                grow[70] = 0u; grow[71] = 0u;
            }
        }
    }
    __syncthreads();

    int lane = tid & 31, wid = tid >> 5;
    int wm = wid & 3, wn = wid >> 2;
    int gid = lane >> 2, t4 = lane & 3;

    float acc[2][4][4];
#pragma unroll
    for (int mt = 0; mt < 2; ++mt)
#pragma unroll
        for (int nt = 0; nt < 4; ++nt)
#pragma unroll
            for (int j = 0; j < 4; ++j) acc[mt][nt][j] = 0.0f;

    const unsigned* Ab = As + (wm * 32 + gid) * PA1 + t4;
    const unsigned* Bb = Ws + (wn * 32 + gid) * PA1 + t4;

#pragma unroll
    for (int ks = 0; ks < KS1; ++ks) {
        int k0 = ks * 8;
        unsigned a[2][4];
#pragma unroll
        for (int mt = 0; mt < 2; ++mt) {
            const unsigned* ap = Ab + mt * 16 * PA1 + k0;
            a[mt][0] = ap[0];
            a[mt][1] = ap[8 * PA1];
            a[mt][2] = ap[4];
            a[mt][3] = ap[8 * PA1 + 4];
        }
#pragma unroll
        for (int nt = 0; nt < 4; ++nt) {
            const unsigned* bp = Bb + nt * 8 * PA1 + k0;
            unsigned b0 = bp[0], b1 = bp[4];
            mma_tf32(acc[0][nt], a[0][0], a[0][1], a[0][2], a[0][3], b0, b1);
            mma_tf32(acc[1][nt], a[1][0], a[1][1], a[1][2], a[1][3], b0, b1);
        }
    }

#pragma unroll
    for (int mt = 0; mt < 2; ++mt) {
        int rbase = row0 + wm * 32 + mt * 16 + gid;
#pragma unroll
        for (int nt = 0; nt < 4; ++nt) {
            int cc = wn * 32 + nt * 8 + t4 * 2;
            *(float2*)(X0 + (size_t)rbase * 128 + cc) =
                make_float2(acc[mt][nt][0], acc[mt][nt][1]);
            *(float2*)(X0 + (size_t)(rbase + 8) * 128 + cc) =
                make_float2(acc[mt][nt][2], acc[mt][nt][3]);
        }
    }
#pragma unroll
    for (int nt = 0; nt < 4; ++nt) {
#pragma unroll
        for (int j = 0; j < 2; ++j) {
            float v0 = acc[0][nt][j], v1 = acc[0][nt][j + 2];
            float v2 = acc[1][nt][j], v3 = acc[1][nt][j + 2];
            float s = v0 + v1 + v2 + v3;
            float q = v0 * v0 + v1 * v1 + v2 * v2 + v3 * v3;
#pragma unroll
            for (int o = 4; o <= 16; o <<= 1) {
                s += __shfl_xor_sync(0xFFFFFFFFu, s, o);
                q += __shfl_xor_sync(0xFFFFFFFFu, q, o);
            }
            if (gid == 0) {
                int c = wn * 32 + nt * 8 + t4 * 2 + j;
                atomicAdd(&s_sum[c], s);
                atomicAdd(&s_sq[c], q);
            }
        }
    }
    __syncthreads();
    if (tid < 128) {
        atomicAdd(&sum_out[tid], s_sum[tid]);
        atomicAdd(&sq_out[tid], s_sq[tid]);
    }
}

// ---------------------------------------------------------------------------
// GEMM2 (per-scale, N-split): block = 128 rows x 64 cols (nhalf = bid&1).
// 512 threads, 16 warps (4m x 4n), warp tile 32x16, acc[2][2][4].
// Smem: A[128][132] + W[64][132] + 384 floats = ~101 KB -> 2 CTAs/SM.
// X1 tile stays in registers: raw max/min pooled + stats; no X1 store.
// ---------------------------------------------------------------------------
#define PA2 132
#define KS2 16
#define SMEM2B ((128 * PA2 + 64 * PA2 + 384) * 4)

template <int NS>
__global__ __launch_bounds__(512, 2) void gemm2_tc(
    const float* __restrict__ Xin, const float* __restrict__ w1,
    const float* __restrict__ gamma, const float* __restrict__ beta,
    float invR, const float* __restrict__ sum_in,
    const float* __restrict__ sq_in, float* __restrict__ sum_out,
    float* __restrict__ sq_out, float* __restrict__ mxp,
    float* __restrict__ mnp) {
    extern __shared__ unsigned sh[];
    unsigned* As = sh;               // [128][132]
    unsigned* Ws = sh + 128 * PA2;   // [64][132]
    float* s_sum = (float*)(sh + 128 * PA2 + 64 * PA2);  // [64]
    float* s_sq  = s_sum + 64;                           // [64]
    float* sc    = s_sq + 64;                            // [128]
    float* sf    = sc + 128;                             // [128]
    int tid = threadIdx.x;
    int nhalf = blockIdx.x & 1;
    int lb    = blockIdx.x >> 1;

    if (tid < 128) {
        float mean = sum_in[tid] * invR;
        float var  = sq_in[tid] * invR - mean * mean;
        float s    = gamma[tid] * rsqrtf(var + 1e-5f);
        sc[tid] = s;
        sf[tid] = fmaf(-mean, s, beta[tid]);
    } else if (tid < 192) {
        s_sum[tid - 128] = 0.0f;
        s_sq[tid - 128]  = 0.0f;
    }
    // stage W half: rows nhalf*64 .. +63
    for (int i = tid; i < 64 * 128; i += 512) {
        int o = i >> 7, k = i & 127;
        Ws[o * PA2 + k] = f2tf(w1[(nhalf * 64 + o) * 128 + k]);
    }
    __syncthreads();

    int row0 = lb * 128;
    for (int i = tid; i < 128 * 32; i += 512) {
        int r = i >> 5, kq = (i & 31) << 2;
        float4 v = *(const float4*)(Xin + (size_t)(row0 + r) * 128 + kq);
        uint4 uu;
        uu.x = f2tf(fmaxf(fmaf(sc[kq + 0], v.x, sf[kq + 0]), 0.0f));
        uu.y = f2tf(fmaxf(fmaf(sc[kq + 1], v.y, sf[kq + 1]), 0.0f));
        uu.z = f2tf(fmaxf(fmaf(sc[kq + 2], v.z, sf[kq + 2]), 0.0f));
        uu.w = f2tf(fmaxf(fmaf(sc[kq + 3], v.w, sf[kq + 3]), 0.0f));
        *(uint4*)(As + r * PA2 + kq) = uu;
    }
    __syncthreads();

    int lane = tid & 31, wid = tid >> 5;
    int wm = wid & 3, wn = wid >> 2;       // wn 0..3 over 64 cols (16 each)
    int gid = lane >> 2, t4 = lane & 3;

    float acc[2][2][4];
#pragma unroll
    for (int mt = 0; mt < 2; ++mt)
#pragma unroll
        for (int nt = 0; nt < 2; ++nt)
#pragma unroll
            for (int j = 0; j < 4; ++j) acc[mt][nt][j] = 0.0f;

    const unsigned* Ab = As + (wm * 32 + gid) * PA2 + t4;
    const unsigned* Bb = Ws + (wn * 16 + gid) * PA2 + t4;

#pragma unroll
    for (int ks = 0; ks < KS2; ++ks) {
        int k0 = ks * 8;
        unsigned a[2][4];
#pragma unroll
        for (int mt = 0; mt < 2; ++mt) {
            const unsigned* ap = Ab + mt * 16 * PA2 + k0;
            a[mt][0] = ap[0];
            a[mt][1] = ap[8 * PA2];
            a[mt][2] = ap[4];
            a[mt][3] = ap[8 * PA2 + 4];
        }
#pragma unroll
        for (int nt = 0; nt < 2; ++nt) {
            const unsigned* bp = Bb + nt * 8 * PA2 + k0;
            unsigned b0 = bp[0], b1 = bp[4];
            mma_tf32(acc[0][nt], a[0][0], a[0][1], a[0][2], a[0][3], b0, b1);
            mma_tf32(acc[1][nt], a[1][0], a[1][1], a[1][2], a[1][3], b0, b1);
        }
    }

    // ---- fused pooling + stats ----
#pragma unroll
    for (int nt = 0; nt < 2; ++nt) {
#pragma unroll
        for (int j = 0; j < 2; ++j) {
            int cl = wn * 16 + nt * 8 + t4 * 2 + j;   // 0..63
            if (NS == 16) {
#pragma unroll
                for (int mt = 0; mt < 2; ++mt) {
                    float mx = fmaxf(acc[mt][nt][j], acc[mt][nt][j + 2]);
                    float mn = fminf(acc[mt][nt][j], acc[mt][nt][j + 2]);
#pragma unroll
                    for (int o = 4; o <= 16; o <<= 1) {
                        mx = fmaxf(mx, __shfl_xor_sync(0xFFFFFFFFu, mx, o));
                        mn = fminf(mn, __shfl_xor_sync(0xFFFFFFFFu, mn, o));
                    }
                    if (gid == 0) {
                        int mq = lb * 8 + wm * 2 + mt;
                        mxp[mq * 128 + nhalf * 64 + cl] = mx;
                        mnp[mq * 128 + nhalf * 64 + cl] = mn;
                    }
                }
            } else {
                float mx = fmaxf(fmaxf(acc[0][nt][j], acc[0][nt][j + 2]),
                                 fmaxf(acc[1][nt][j], acc[1][nt][j + 2]));
                float mn = fminf(fminf(acc[0][nt][j], acc[0][nt][j + 2]),
                                 fminf(acc[1][nt][j], acc[1][nt][j + 2]));
#pragma unroll
                for (int o = 4; o <= 16; o <<= 1) {
                    mx = fmaxf(mx, __shfl_xor_sync(0xFFFFFFFFu, mx, o));
                    mn = fminf(mn, __shfl_xor_sync(0xFFFFFFFFu, mn, o));
                }
                if (gid == 0) {
                    int mq = lb * 4 + wm;
                    mxp[mq * 128 + nhalf * 64 + cl] = mx;
                    mnp[mq * 128 + nhalf * 64 + cl] = mn;
                }
            }
            float v0 = acc[0][nt][j], v1 = acc[0][nt][j + 2];
            float v2 = acc[1][nt][j], v3 = acc[1][nt][j + 2];
            float s = v0 + v1 + v2 + v3;
            float q = v0 * v0 + v1 * v1 + v2 * v2 + v3 * v3;
#pragma unroll
            for (int o = 4; o <= 16; o <<= 1) {
                s += __shfl_xor_sync(0xFFFFFFFFu, s, o);
                q += __shfl_xor_sync(0xFFFFFFFFu, q, o);
            }
            if (gid == 0) {
                atomicAdd(&s_sum[cl], s);
                atomicAdd(&s_sq[cl], q);
            }
        }
    }
    __syncthreads();
    if (tid < 64) {
        atomicAdd(&sum_out[nhalf * 64 + tid], s_sum[tid]);
        atomicAdd(&sq_out[nhalf * 64 + tid], s_sq[tid]);
    }
}

// ---------------------------------------------------------------------------
// Final: BN finalize inline on pooled raw values; pick max/min by sign(s).
// ---------------------------------------------------------------------------
__global__ void poolout(float* __restrict__ out, const float* __restrict__ g01,
                        const float* __restrict__ b01,
                        const float* __restrict__ g11,
                        const float* __restrict__ b11, float invR0,
                        float invR1) {
    int t = blockIdx.x * blockDim.x + threadIdx.x;
    int scl = t >= MTOT * 128;
    int tt = t - scl * MTOT * 128;
    int m = tt >> 7;
    int c = tt & 127;
    const float* sum_in = g_sumA + (scl ? 384 : 128);
    const float* sq_in  = g_sqA + (scl ? 384 : 128);
    const float* gamma = scl ? g11 : g01;
    const float* beta  = scl ? b11 : b01;
    float invR = scl ? invR1 : invR0;

    float mean = sum_in[c] * invR;
    float var  = sq_in[c] * invR - mean * mean;
    float s    = gamma[c] * rsqrtf(var + 1e-5f);
    float b    = fmaf(-mean, s, beta[c]);
    float mx = (scl ? g_mx1 : g_mx0)[tt];
    float mn = (scl ? g_mn1 : g_mn0)[tt];
    float v = (s >= 0.0f) ? mx : mn;
    out[(size_t)m * 256 + (scl ? 128 : 0) + c] = fmaxf(fmaf(s, v, b), 0.0f);
}

// ---------------------------------------------------------------------------
extern "C" void kernel_launch(void* const* d_in, const int* in_sizes, int n_in,
                              void* d_out, int out_size) {
    const float* xyz  = (const float*)d_in[0];
    const float* feat = (const float*)d_in[1];
    const float* nxyz = (const float*)d_in[2];
    const float* w00 = (const float*)d_in[5];
    const float* g00 = (const float*)d_in[6];
    const float* b00 = (const float*)d_in[7];
    const float* w01 = (const float*)d_in[8];
    const float* g01 = (const float*)d_in[9];
    const float* b01 = (const float*)d_in[10];
    const float* w10 = (const float*)d_in[11];
    const float* g10 = (const float*)d_in[12];
    const float* b10 = (const float*)d_in[13];
    const float* w11 = (const float*)d_in[14];
    const float* g11 = (const float*)d_in[15];
    const float* b11 = (const float*)d_in[16];

    float* outBase = (float*)d_out;
    int featOff = out_size - MTOT * 256;
    if (featOff < 0) featOff = 0;
    float* outF = outBase + featOff;

    cudaFuncSetAttribute(gemm1_merged,
                         cudaFuncAttributeMaxDynamicSharedMemorySize, SMEM1B);
    cudaFuncSetAttribute(gemm2_tc<16>,
                         cudaFuncAttributeMaxDynamicSharedMemorySize, SMEM2B);
    cudaFuncSetAttribute(gemm2_tc<32>,
                         cudaFuncAttributeMaxDynamicSharedMemorySize, SMEM2B);

    float* X0a;
    float* X0b;
    float* sumA;
    float* sqA;
    float* mx0;
    float* mn0;
    float* mx1;
    float* mn1;
    cudaGetSymbolAddress((void**)&X0a, g_X0a);
    cudaGetSymbolAddress((void**)&X0b, g_X0b);
    cudaGetSymbolAddress((void**)&sumA, g_sumA);
    cudaGetSymbolAddress((void**)&sqA, g_sqA);
    cudaGetSymbolAddress((void**)&mx0, g_mx0);
    cudaGetSymbolAddress((void**)&mn0, g_mn0);
    cudaGetSymbolAddress((void**)&mx1, g_mx1);
    cudaGetSymbolAddress((void**)&mn1, g_mn1);

    const float r2_0 = (float)(0.2 * 0.2);
    const float r2_1 = (float)(0.4 * 0.4);
    const float invR0 = 1.0f / 131072.0f;
    const float invR1 = 1.0f / 262144.0f;

    ballquery_merged<<<2048, 256>>>(xyz, nxyz, r2_0, r2_1, nxyz, outBase,
                                    featOff);
    gemm1_merged<<<3072, 512, SMEM1B>>>(xyz, feat, nxyz, w00, w10);
    // scale 1 first: gemm1's last-written X0b tail is still L2-resident
    gemm2_tc<32><<<4096, 512, SMEM2B>>>(X0b, w11, g10, b10, invR1, sumA + 256,
                                        sqA + 256, sumA + 384, sqA + 384, mx1,
                                        mn1);
    gemm2_tc<16><<<2048, 512, SMEM2B>>>(X0a, w01, g00, b00, invR0, sumA + 0,
                                        sqA + 0, sumA + 128, sqA + 128, mx0,
                                        mn0);
    poolout<<<2 * MTOT * 128 / 256, 256>>>(outF, g01, b01, g11, b11, invR0,
                                           invR1);
}

// round 12
// speedup vs baseline: 1.1691x; 1.1691x over previous
#include <cuda_runtime.h>
#include <cstddef>

// ---------------------------------------------------------------------------
// StackSAModuleMSG — tf32 tensor cores; multi-tile blocks + paired-column
// smem (LDS.64 fragment loads). X1 never touches DRAM (fused raw max/min).
// B=4, NB=8192, MB=2048, M=8192, C_IN=64, CIN=67 (K padded to 72).
// Scale 0: r=0.2, NS=16 (R=131072).  Scale 1: r=0.4, NS=32 (R=262144).
//
// Paired-column layout: within each 8-col group, column c sits at slot
// (c&~7) + 2*(c&3) + ((c>>2)&1), so (k, k+4) are adjacent -> one LDS.64
// per fragment pair. Pitches 72 / 136 (== 8 mod 32) keep LDS.64 loads
// bank-conflict-free per 16-lane phase.
// ---------------------------------------------------------------------------

#define MTOT 8192
#define NPB  8192

__device__ float g_X0a[131072 * 128];
__device__ float g_X0b[262144 * 128];
__device__ int   g_idx0[8192 * 16];
__device__ int   g_idx1[8192 * 32];
__device__ float g_mx0[8192 * 128];
__device__ float g_mn0[8192 * 128];
__device__ float g_mx1[8192 * 128];
__device__ float g_mn1[8192 * 128];
__device__ float g_sumA[512];   // slots: 0=g1/s0, 1=g2/s0, 2=g1/s1, 3=g2/s1
__device__ float g_sqA[512];

__device__ __forceinline__ unsigned f2tf(float f) {
    unsigned r;
    asm("cvt.rna.tf32.f32 %0, %1;" : "=r"(r) : "f"(f));
    return r;
}

__device__ __forceinline__ int slotf(int c) {
    return (c & ~7) + ((c & 3) * 2) + ((c >> 2) & 1);
}

__device__ __forceinline__ void mma_tf32(float* c, unsigned a0, unsigned a1,
                                         unsigned a2, unsigned a3, unsigned b0,
                                         unsigned b1) {
    asm volatile(
        "mma.sync.aligned.m16n8k8.row.col.f32.tf32.tf32.f32 "
        "{%0,%1,%2,%3}, {%4,%5,%6,%7}, {%8,%9}, {%0,%1,%2,%3};"
        : "+f"(c[0]), "+f"(c[1]), "+f"(c[2]), "+f"(c[3])
        : "r"(a0), "r"(a1), "r"(a2), "r"(a3), "r"(b0), "r"(b1));
}

// ---------------------------------------------------------------------------
// Merged ball query (exact fp32; folds stats zeroing + new_xyz copy).
// ---------------------------------------------------------------------------
__global__ void ballquery_merged(const float* __restrict__ xyz,
                                 const float* __restrict__ newxyz,
                                 float r2_0, float r2_1,
                                 const float* __restrict__ copySrc,
                                 float* __restrict__ copyDst, int copyN) {
    int tid = threadIdx.x;
    if (blockIdx.x == 0) {
        g_sumA[tid] = 0.0f; g_sumA[tid + 256] = 0.0f;
        g_sqA[tid]  = 0.0f; g_sqA[tid + 256]  = 0.0f;
    }
    int ct = blockIdx.x * 256 + tid;
    if (ct < copyN) copyDst[ct] = copySrc[ct];

    int gw   = (blockIdx.x * 256 + tid) >> 5;
    int lane = tid & 31;
    if (gw >= 2 * MTOT) return;
    int scl = gw >> 13;
    int q   = gw & (MTOT - 1);
    int NS  = scl ? 32 : 16;
    float r2 = scl ? r2_1 : r2_0;
    int* idx_out = (scl ? g_idx1 : g_idx0) + q * NS;

    int b = q >> 11;
    float qx = newxyz[q * 3 + 0];
    float qy = newxyz[q * 3 + 1];
    float qz = newxyz[q * 3 + 2];
    float qq = __fadd_rn(__fadd_rn(__fmul_rn(qx, qx), __fmul_rn(qy, qy)),
                         __fmul_rn(qz, qz));
    const float* P = xyz + (size_t)b * NPB * 3;
    int cnt = 0, first = -1;
    for (int start = 0; start < NPB; start += 32) {
        int i = start + lane;
        float px = P[i * 3 + 0];
        float py = P[i * 3 + 1];
        float pz = P[i * 3 + 2];
        float pp = __fadd_rn(__fadd_rn(__fmul_rn(px, px), __fmul_rn(py, py)),
                             __fmul_rn(pz, pz));
        float dt = __fadd_rn(__fadd_rn(__fmul_rn(qx, px), __fmul_rn(qy, py)),
                             __fmul_rn(qz, pz));
        float d2 = __fsub_rn(__fadd_rn(qq, pp), __fmul_rn(2.0f, dt));
        bool in = d2 < r2;
        unsigned mask = __ballot_sync(0xFFFFFFFFu, in);
        if (mask) {
            if (first < 0) first = start + (__ffs(mask) - 1);
            int pos = cnt + __popc(mask & ((1u << lane) - 1u));
            if (in && pos < NS) idx_out[pos] = i;
            cnt += __popc(mask);
            if (cnt >= NS) break;
        }
    }
    if (cnt == 0) {
        for (int j = lane; j < NS; j += 32) idx_out[j] = -1;
    } else if (cnt < NS) {
        for (int j = cnt + lane; j < NS; j += 32) idx_out[j] = first;
    }
}

// ---------------------------------------------------------------------------
// GEMM1: X0[R,128] = gather(G)[R,67] @ W0^T. 512 thr, 16 warps (4m x 4n),
// warp 32x32, block 128x128, 2 row-tiles per block (W staged once).
// Paired-column layout, pitch 72: frag pair = 1 LDS.64.
// ---------------------------------------------------------------------------
#define PA1 72
#define KS1 9
#define TILES1 2
#define SMEM1B ((128 * PA1 * 2 + 256) * 4)

__global__ __launch_bounds__(512, 2) void gemm1_merged(
    const float* __restrict__ xyz, const float* __restrict__ feat,
    const float* __restrict__ newxyz, const float* __restrict__ w00,
    const float* __restrict__ w10) {
    extern __shared__ unsigned sh[];
    unsigned* As = sh;              // [128][72] paired
    unsigned* Ws = sh + 128 * PA1;  // [128][72] paired (W[o][c])
    float* s_sum = (float*)(sh + 2 * 128 * PA1);
    float* s_sq  = s_sum + 128;
    int tid = threadIdx.x;
    int bid = blockIdx.x;
    int scl = bid >= 512;
    int lb0 = (scl ? bid - 512 : bid) * TILES1;
    int nsShift = scl ? 5 : 4;
    const int* idx = scl ? g_idx1 : g_idx0;
    const float* w0 = scl ? w10 : w00;
    float* X0 = scl ? g_X0b : g_X0a;
    float* sum_out = g_sumA + (scl ? 256 : 0);
    float* sq_out  = g_sqA + (scl ? 256 : 0);

    if (tid < 128) { s_sum[tid] = 0.0f; s_sq[tid] = 0.0f; }
    for (int i = tid; i < 128 * PA1; i += 512) {
        int o = i / PA1;
        int c = i - o * PA1;
        Ws[o * PA1 + slotf(c)] = (c < 67) ? f2tf(w0[o * 67 + c]) : 0u;
    }

    int lane = tid & 31, wid = tid >> 5;
    int wm = wid & 3, wn = wid >> 2;
    int gid = lane >> 2, t4 = lane & 3;
    const uint2* Ap = (const uint2*)(As + (wm * 32 + gid) * PA1 + 2 * t4);
    const uint2* Bp = (const uint2*)(Ws + (wn * 32 + gid) * PA1 + 2 * t4);

    for (int t = 0; t < TILES1; ++t) {
        if (t) __syncthreads();
        int row0 = (lb0 + t) * 128;
        {
            int r = tid >> 2, lw = tid & 3;
            int rg = row0 + r;
            int m  = rg >> nsShift;
            int p  = idx[rg];
            unsigned* grow = As + r * PA1;
            if (p < 0) {
#pragma unroll
                for (int c = lw * 18; c < lw * 18 + 18; ++c) grow[c] = 0u;
            } else {
                int gp = ((m >> 11) << 13) + p;
                if (lw == 0) {
                    grow[0] = f2tf(xyz[gp * 3 + 0] - newxyz[m * 3 + 0]);
                    grow[2] = f2tf(xyz[gp * 3 + 1] - newxyz[m * 3 + 1]);
                    grow[4] = f2tf(xyz[gp * 3 + 2] - newxyz[m * 3 + 2]);
                }
                const float4* frow = (const float4*)(feat + (size_t)gp * 64);
#pragma unroll
                for (int j = 0; j < 4; ++j) {
                    int f = lw + 4 * j;
                    float4 v = frow[f];
                    grow[slotf(3 + 4 * f + 0)] = f2tf(v.x);
                    grow[slotf(3 + 4 * f + 1)] = f2tf(v.y);
                    grow[slotf(3 + 4 * f + 2)] = f2tf(v.z);
                    grow[slotf(3 + 4 * f + 3)] = f2tf(v.w);
                }
                if (lw == 3) {
                    grow[70] = 0u; grow[65] = 0u; grow[67] = 0u;
                    grow[69] = 0u; grow[71] = 0u;
                }
            }
        }
        __syncthreads();

        float acc[2][4][4];
#pragma unroll
        for (int mt = 0; mt < 2; ++mt)
#pragma unroll
            for (int nt = 0; nt < 4; ++nt)
#pragma unroll
                for (int j = 0; j < 4; ++j) acc[mt][nt][j] = 0.0f;

#pragma unroll
        for (int ks = 0; ks < KS1; ++ks) {
            uint2 a0 = Ap[ks * 4];
            uint2 a1 = Ap[8 * (PA1 / 2) + ks * 4];
            uint2 a2 = Ap[8 * PA1 + ks * 4];
            uint2 a3 = Ap[8 * PA1 + 8 * (PA1 / 2) + ks * 4];
#pragma unroll
            for (int nt = 0; nt < 4; ++nt) {
                uint2 b = Bp[nt * 4 * PA1 + ks * 4];
                mma_tf32(acc[0][nt], a0.x, a1.x, a0.y, a1.y, b.x, b.y);
                mma_tf32(acc[1][nt], a2.x, a3.x, a2.y, a3.y, b.x, b.y);
            }
        }

#pragma unroll
        for (int mt = 0; mt < 2; ++mt) {
            int rbase = row0 + wm * 32 + mt * 16 + gid;
#pragma unroll
            for (int nt = 0; nt < 4; ++nt) {
                int cc = wn * 32 + nt * 8 + t4 * 2;
                *(float2*)(X0 + (size_t)rbase * 128 + cc) =
                    make_float2(acc[mt][nt][0], acc[mt][nt][1]);
                *(float2*)(X0 + (size_t)(rbase + 8) * 128 + cc) =
                    make_float2(acc[mt][nt][2], acc[mt][nt][3]);
            }
        }
#pragma unroll
        for (int nt = 0; nt < 4; ++nt) {
#pragma unroll
            for (int j = 0; j < 2; ++j) {
                float v0 = acc[0][nt][j], v1 = acc[0][nt][j + 2];
                float v2 = acc[1][nt][j], v3 = acc[1][nt][j + 2];
                float s = v0 + v1 + v2 + v3;
                float q = v0 * v0 + v1 * v1 + v2 * v2 + v3 * v3;
#pragma unroll
                for (int o = 4; o <= 16; o <<= 1) {
                    s += __shfl_xor_sync(0xFFFFFFFFu, s, o);
                    q += __shfl_xor_sync(0xFFFFFFFFu, q, o);
                }
                if (gid == 0) {
                    int c = wn * 32 + nt * 8 + t4 * 2 + j;
                    atomicAdd(&s_sum[c], s);
                    atomicAdd(&s_sq[c], q);
                }
            }
        }
    }
    __syncthreads();
    if (tid < 128) {
        atomicAdd(&sum_out[tid], s_sum[tid]);
        atomicAdd(&sq_out[tid], s_sq[tid]);
    }
}

// ---------------------------------------------------------------------------
// GEMM2 (per-scale): block 128x128, 2 row-tiles per block; W + sc/sf staged
// once. A: proven uint4/LDS.32 path (pitch 132). W: paired layout pitch 136,
// conflict-free STS.64 staging, 1 LDS.64 per B-frag. X1 stays in registers:
// raw max/min pooling + stats fused; no X1 store.
// ---------------------------------------------------------------------------
#define PA2 132
#define PW2 136
#define KS2 16
#define TILES2 2
#define SMEM2B ((128 * PA2 + 128 * PW2 + 512) * 4)

template <int NS>
__global__ __launch_bounds__(512) void gemm2_tc(
    const float* __restrict__ Xin, const float* __restrict__ w1,
    const float* __restrict__ gamma, const float* __restrict__ beta,
    float invR, const float* __restrict__ sum_in,
    const float* __restrict__ sq_in, float* __restrict__ sum_out,
    float* __restrict__ sq_out, float* __restrict__ mxp,
    float* __restrict__ mnp) {
    extern __shared__ unsigned sh[];
    unsigned* As = sh;               // [128][132]
    unsigned* Ws = sh + 128 * PA2;   // [128][136] paired
    float* s_sum = (float*)(sh + 128 * PA2 + 128 * PW2);
    float* s_sq  = s_sum + 128;
    float* sc    = s_sq + 128;
    float* sf    = sc + 128;
    int tid = threadIdx.x;
    int lb0 = blockIdx.x * TILES2;

    if (tid < 128) {
        s_sum[tid] = 0.0f;
        s_sq[tid]  = 0.0f;
        float mean = sum_in[tid] * invR;
        float var  = sq_in[tid] * invR - mean * mean;
        float s    = gamma[tid] * rsqrtf(var + 1e-5f);
        sc[tid] = s;
        sf[tid] = fmaf(-mean, s, beta[tid]);
    }
    // stage W in paired layout via conflict-free STS.64:
    // pair index p -> columns c=(p>>2)*8+(p&3) and c+4, slot (p>>2)*8+2*(p&3)
    for (int i = tid; i < 128 * 64; i += 512) {
        int o = i >> 6, p = i & 63;
        int c = ((p >> 2) << 3) + (p & 3);
        uint2 u;
        u.x = f2tf(w1[o * 128 + c]);
        u.y = f2tf(w1[o * 128 + c + 4]);
        *(uint2*)(Ws + o * PW2 + ((p >> 2) << 3) + 2 * (p & 3)) = u;
    }
    __syncthreads();

    int lane = tid & 31, wid = tid >> 5;
    int wm = wid & 3, wn = wid >> 2;
    int gid = lane >> 2, t4 = lane & 3;
    const unsigned* Ab = As + (wm * 32 + gid) * PA2 + t4;
    const uint2* Bp = (const uint2*)(Ws + (wn * 32 + gid) * PW2 + 2 * t4);

    for (int t = 0; t < TILES2; ++t) {
        if (t) __syncthreads();
        int row0 = (lb0 + t) * 128;
        for (int i = tid; i < 128 * 32; i += 512) {
            int r = i >> 5, kq = (i & 31) << 2;
            float4 v = *(const float4*)(Xin + (size_t)(row0 + r) * 128 + kq);
            uint4 uu;
            uu.x = f2tf(fmaxf(fmaf(sc[kq + 0], v.x, sf[kq + 0]), 0.0f));
            uu.y = f2tf(fmaxf(fmaf(sc[kq + 1], v.y, sf[kq + 1]), 0.0f));
            uu.z = f2tf(fmaxf(fmaf(sc[kq + 2], v.z, sf[kq + 2]), 0.0f));
            uu.w = f2tf(fmaxf(fmaf(sc[kq + 3], v.w, sf[kq + 3]), 0.0f));
            *(uint4*)(As + r * PA2 + kq) = uu;
        }
        __syncthreads();

        float acc[2][4][4];
#pragma unroll
        for (int mt = 0; mt < 2; ++mt)
#pragma unroll
            for (int nt = 0; nt < 4; ++nt)
#pragma unroll
                for (int j = 0; j < 4; ++j) acc[mt][nt][j] = 0.0f;

#pragma unroll
        for (int ks = 0; ks < KS2; ++ks) {
            int k0 = ks * 8;
            unsigned a[2][4];
#pragma unroll
            for (int mt = 0; mt < 2; ++mt) {
                const unsigned* ap = Ab + mt * 16 * PA2 + k0;
                a[mt][0] = ap[0];
                a[mt][1] = ap[8 * PA2];
                a[mt][2] = ap[4];
                a[mt][3] = ap[8 * PA2 + 4];
            }
#pragma unroll
            for (int nt = 0; nt < 4; ++nt) {
                uint2 b = Bp[nt * 4 * PW2 + ks * 4];
                mma_tf32(acc[0][nt], a[0][0], a[0][1], a[0][2], a[0][3], b.x,
                         b.y);
                mma_tf32(acc[1][nt], a[1][0], a[1][1], a[1][2], a[1][3], b.x,
                         b.y);
            }
        }

        // ---- fused pooling + stats ----
#pragma unroll
        for (int nt = 0; nt < 4; ++nt) {
#pragma unroll
            for (int j = 0; j < 2; ++j) {
                int c = wn * 32 + nt * 8 + t4 * 2 + j;
                if (NS == 16) {
#pragma unroll
                    for (int mt = 0; mt < 2; ++mt) {
                        float mx = fmaxf(acc[mt][nt][j], acc[mt][nt][j + 2]);
                        float mn = fminf(acc[mt][nt][j], acc[mt][nt][j + 2]);
#pragma unroll
                        for (int o = 4; o <= 16; o <<= 1) {
                            mx = fmaxf(mx,
                                       __shfl_xor_sync(0xFFFFFFFFu, mx, o));
                            mn = fminf(mn,
                                       __shfl_xor_sync(0xFFFFFFFFu, mn, o));
                        }
                        if (gid == 0) {
                            int mq = (lb0 + t) * 8 + wm * 2 + mt;
                            mxp[mq * 128 + c] = mx;
                            mnp[mq * 128 + c] = mn;
                        }
                    }
                } else {
                    float mx = fmaxf(fmaxf(acc[0][nt][j], acc[0][nt][j + 2]),
                                     fmaxf(acc[1][nt][j], acc[1][nt][j + 2]));
                    float mn = fminf(fminf(acc[0][nt][j], acc[0][nt][j + 2]),
                                     fminf(acc[1][nt][j], acc[1][nt][j + 2]));
#pragma unroll
                    for (int o = 4; o <= 16; o <<= 1) {
                        mx = fmaxf(mx, __shfl_xor_sync(0xFFFFFFFFu, mx, o));
                        mn = fminf(mn, __shfl_xor_sync(0xFFFFFFFFu, mn, o));
                    }
                    if (gid == 0) {
                        int mq = (lb0 + t) * 4 + wm;
                        mxp[mq * 128 + c] = mx;
                        mnp[mq * 128 + c] = mn;
                    }
                }
                float v0 = acc[0][nt][j], v1 = acc[0][nt][j + 2];
                float v2 = acc[1][nt][j], v3 = acc[1][nt][j + 2];
                float s = v0 + v1 + v2 + v3;
                float q = v0 * v0 + v1 * v1 + v2 * v2 + v3 * v3;
#pragma unroll
                for (int o = 4; o <= 16; o <<= 1) {
                    s += __shfl_xor_sync(0xFFFFFFFFu, s, o);
                    q += __shfl_xor_sync(0xFFFFFFFFu, q, o);
                }
                if (gid == 0) {
                    atomicAdd(&s_sum[c], s);
                    atomicAdd(&s_sq[c], q);
                }
            }
        }
    }
    __syncthreads();
    if (tid < 128) {
        atomicAdd(&sum_out[tid], s_sum[tid]);
        atomicAdd(&sq_out[tid], s_sq[tid]);
    }
}

// ---------------------------------------------------------------------------
// Final: BN finalize inline on pooled raw values; pick max/min by sign(s).
// ---------------------------------------------------------------------------
__global__ void poolout(float* __restrict__ out, const float* __restrict__ g01,
                        const float* __restrict__ b01,
                        const float* __restrict__ g11,
                        const float* __restrict__ b11, float invR0,
                        float invR1) {
    int t = blockIdx.x * blockDim.x + threadIdx.x;
    int scl = t >= MTOT * 128;
    int tt = t - scl * MTOT * 128;
    int m = tt >> 7;
    int c = tt & 127;
    const float* sum_in = g_sumA + (scl ? 384 : 128);
    const float* sq_in  = g_sqA + (scl ? 384 : 128);
    const float* gamma = scl ? g11 : g01;
    const float* beta  = scl ? b11 : b01;
    float invR = scl ? invR1 : invR0;

    float mean = sum_in[c] * invR;
    float var  = sq_in[c] * invR - mean * mean;
    float s    = gamma[c] * rsqrtf(var + 1e-5f);
    float b    = fmaf(-mean, s, beta[c]);
    float mx = (scl ? g_mx1 : g_mx0)[tt];
    float mn = (scl ? g_mn1 : g_mn0)[tt];
    float v = (s >= 0.0f) ? mx : mn;
    out[(size_t)m * 256 + (scl ? 128 : 0) + c] = fmaxf(fmaf(s, v, b), 0.0f);
}

// ---------------------------------------------------------------------------
extern "C" void kernel_launch(void* const* d_in, const int* in_sizes, int n_in,
                              void* d_out, int out_size) {
    const float* xyz  = (const float*)d_in[0];
    const float* feat = (const float*)d_in[1];
    const float* nxyz = (const float*)d_in[2];
    const float* w00 = (const float*)d_in[5];
    const float* g00 = (const float*)d_in[6];
    const float* b00 = (const float*)d_in[7];
    const float* w01 = (const float*)d_in[8];
    const float* g01 = (const float*)d_in[9];
    const float* b01 = (const float*)d_in[10];
    const float* w10 = (const float*)d_in[11];
    const float* g10 = (const float*)d_in[12];
    const float* b10 = (const float*)d_in[13];
    const float* w11 = (const float*)d_in[14];
    const float* g11 = (const float*)d_in[15];
    const float* b11 = (const float*)d_in[16];

    float* outBase = (float*)d_out;
    int featOff = out_size - MTOT * 256;
    if (featOff < 0) featOff = 0;
    float* outF = outBase + featOff;

    cudaFuncSetAttribute(gemm1_merged,
                         cudaFuncAttributeMaxDynamicSharedMemorySize, SMEM1B);
    cudaFuncSetAttribute(gemm2_tc<16>,
                         cudaFuncAttributeMaxDynamicSharedMemorySize, SMEM2B);
    cudaFuncSetAttribute(gemm2_tc<32>,
                         cudaFuncAttributeMaxDynamicSharedMemorySize, SMEM2B);

    float* X0a;
    float* X0b;
    float* sumA;
    float* sqA;
    float* mx0;
    float* mn0;
    float* mx1;
    float* mn1;
    cudaGetSymbolAddress((void**)&X0a, g_X0a);
    cudaGetSymbolAddress((void**)&X0b, g_X0b);
    cudaGetSymbolAddress((void**)&sumA, g_sumA);
    cudaGetSymbolAddress((void**)&sqA, g_sqA);
    cudaGetSymbolAddress((void**)&mx0, g_mx0);
    cudaGetSymbolAddress((void**)&mn0, g_mn0);
    cudaGetSymbolAddress((void**)&mx1, g_mx1);
    cudaGetSymbolAddress((void**)&mn1, g_mn1);

    const float r2_0 = (float)(0.2 * 0.2);
    const float r2_1 = (float)(0.4 * 0.4);
    const float invR0 = 1.0f / 131072.0f;
    const float invR1 = 1.0f / 262144.0f;

    ballquery_merged<<<2048, 256>>>(xyz, nxyz, r2_0, r2_1, nxyz, outBase,
                                    featOff);
    // gemm1: 512 blocks scale0 (2 tiles each) + 1024 blocks scale1
    gemm1_merged<<<1536, 512, SMEM1B>>>(xyz, feat, nxyz, w00, w10);
    // scale 1 first: gemm1's last-written X0b tail is still L2-resident
    gemm2_tc<32><<<1024, 512, SMEM2B>>>(X0b, w11, g10, b10, invR1, sumA + 256,
                                        sqA + 256, sumA + 384, sqA + 384, mx1,
                                        mn1);
    gemm2_tc<16><<<512, 512, SMEM2B>>>(X0a, w01, g00, b00, invR0, sumA + 0,
                                       sqA + 0, sumA + 128, sqA + 128, mx0,
                                       mn0);
    poolout<<<2 * MTOT * 128 / 256, 256>>>(outF, g01, b01, g11, b11, invR0,
                                           invR1);
}

// round 13
// speedup vs baseline: 1.2039x; 1.0298x over previous
#include <cuda_runtime.h>
#include <cstddef>

// ---------------------------------------------------------------------------
// StackSAModuleMSG — tf32 tensor cores; multi-tile blocks, paired-column
// smem, register-prefetched A staging in gemm2. X1 never touches DRAM.
// B=4, NB=8192, MB=2048, M=8192, C_IN=64, CIN=67 (K padded to 72).
// Scale 0: r=0.2, NS=16 (R=131072).  Scale 1: r=0.4, NS=32 (R=262144).
// ---------------------------------------------------------------------------

#define MTOT 8192
#define NPB  8192

__device__ float g_X0a[131072 * 128];
__device__ float g_X0b[262144 * 128];
__device__ int   g_idx0[8192 * 16];
__device__ int   g_idx1[8192 * 32];
__device__ float g_mx0[8192 * 128];
__device__ float g_mn0[8192 * 128];
__device__ float g_mx1[8192 * 128];
__device__ float g_mn1[8192 * 128];
__device__ float g_sumA[512];   // slots: 0=g1/s0, 1=g2/s0, 2=g1/s1, 3=g2/s1
__device__ float g_sqA[512];

__device__ __forceinline__ unsigned f2tf(float f) {
    unsigned r;
    asm("cvt.rna.tf32.f32 %0, %1;" : "=r"(r) : "f"(f));
    return r;
}

__device__ __forceinline__ int slotf(int c) {
    return (c & ~7) + ((c & 3) * 2) + ((c >> 2) & 1);
}

__device__ __forceinline__ void mma_tf32(float* c, unsigned a0, unsigned a1,
                                         unsigned a2, unsigned a3, unsigned b0,
                                         unsigned b1) {
    asm volatile(
        "mma.sync.aligned.m16n8k8.row.col.f32.tf32.tf32.f32 "
        "{%0,%1,%2,%3}, {%4,%5,%6,%7}, {%8,%9}, {%0,%1,%2,%3};"
        : "+f"(c[0]), "+f"(c[1]), "+f"(c[2]), "+f"(c[3])
        : "r"(a0), "r"(a1), "r"(a2), "r"(a3), "r"(b0), "r"(b1));
}

// ---------------------------------------------------------------------------
// Merged ball query (exact fp32; folds stats zeroing + new_xyz copy).
// ---------------------------------------------------------------------------
__global__ void ballquery_merged(const float* __restrict__ xyz,
                                 const float* __restrict__ newxyz,
                                 float r2_0, float r2_1,
                                 const float* __restrict__ copySrc,
                                 float* __restrict__ copyDst, int copyN) {
    int tid = threadIdx.x;
    if (blockIdx.x == 0) {
        g_sumA[tid] = 0.0f; g_sumA[tid + 256] = 0.0f;
        g_sqA[tid]  = 0.0f; g_sqA[tid + 256]  = 0.0f;
    }
    int ct = blockIdx.x * 256 + tid;
    if (ct < copyN) copyDst[ct] = copySrc[ct];

    int gw   = (blockIdx.x * 256 + tid) >> 5;
    int lane = tid & 31;
    if (gw >= 2 * MTOT) return;
    int scl = gw >> 13;
    int q   = gw & (MTOT - 1);
    int NS  = scl ? 32 : 16;
    float r2 = scl ? r2_1 : r2_0;
    int* idx_out = (scl ? g_idx1 : g_idx0) + q * NS;

    int b = q >> 11;
    float qx = newxyz[q * 3 + 0];
    float qy = newxyz[q * 3 + 1];
    float qz = newxyz[q * 3 + 2];
    float qq = __fadd_rn(__fadd_rn(__fmul_rn(qx, qx), __fmul_rn(qy, qy)),
                         __fmul_rn(qz, qz));
    const float* P = xyz + (size_t)b * NPB * 3;
    int cnt = 0, first = -1;
    for (int start = 0; start < NPB; start += 32) {
        int i = start + lane;
        float px = P[i * 3 + 0];
        float py = P[i * 3 + 1];
        float pz = P[i * 3 + 2];
        float pp = __fadd_rn(__fadd_rn(__fmul_rn(px, px), __fmul_rn(py, py)),
                             __fmul_rn(pz, pz));
        float dt = __fadd_rn(__fadd_rn(__fmul_rn(qx, px), __fmul_rn(qy, py)),
                             __fmul_rn(qz, pz));
        float d2 = __fsub_rn(__fadd_rn(qq, pp), __fmul_rn(2.0f, dt));
        bool in = d2 < r2;
        unsigned mask = __ballot_sync(0xFFFFFFFFu, in);
        if (mask) {
            if (first < 0) first = start + (__ffs(mask) - 1);
            int pos = cnt + __popc(mask & ((1u << lane) - 1u));
            if (in && pos < NS) idx_out[pos] = i;
            cnt += __popc(mask);
            if (cnt >= NS) break;
        }
    }
    if (cnt == 0) {
        for (int j = lane; j < NS; j += 32) idx_out[j] = -1;
    } else if (cnt < NS) {
        for (int j = cnt + lane; j < NS; j += 32) idx_out[j] = first;
    }
}

// ---------------------------------------------------------------------------
// GEMM1: X0[R,128] = gather(G)[R,67] @ W0^T. 512 thr, 16 warps (4m x 4n),
// warp 32x32, block 128x128, 2 row-tiles per block (W staged once).
// Paired-column layout, pitch 72: frag pair = 1 LDS.64.  (unchanged R12)
// ---------------------------------------------------------------------------
#define PA1 72
#define KS1 9
#define TILES1 2
#define SMEM1B ((128 * PA1 * 2 + 256) * 4)

__global__ __launch_bounds__(512, 2) void gemm1_merged(
    const float* __restrict__ xyz, const float* __restrict__ feat,
    const float* __restrict__ newxyz, const float* __restrict__ w00,
    const float* __restrict__ w10) {
    extern __shared__ unsigned sh[];
    unsigned* As = sh;              // [128][72] paired
    unsigned* Ws = sh + 128 * PA1;  // [128][72] paired (W[o][c])
    float* s_sum = (float*)(sh + 2 * 128 * PA1);
    float* s_sq  = s_sum + 128;
    int tid = threadIdx.x;
    int bid = blockIdx.x;
    int scl = bid >= 512;
    int lb0 = (scl ? bid - 512 : bid) * TILES1;
    int nsShift = scl ? 5 : 4;
    const int* idx = scl ? g_idx1 : g_idx0;
    const float* w0 = scl ? w10 : w00;
    float* X0 = scl ? g_X0b : g_X0a;
    float* sum_out = g_sumA + (scl ? 256 : 0);
    float* sq_out  = g_sqA + (scl ? 256 : 0);

    if (tid < 128) { s_sum[tid] = 0.0f; s_sq[tid] = 0.0f; }
    for (int i = tid; i < 128 * PA1; i += 512) {
        int o = i / PA1;
        int c = i - o * PA1;
        Ws[o * PA1 + slotf(c)] = (c < 67) ? f2tf(w0[o * 67 + c]) : 0u;
    }

    int lane = tid & 31, wid = tid >> 5;
    int wm = wid & 3, wn = wid >> 2;
    int gid = lane >> 2, t4 = lane & 3;
    const uint2* Ap = (const uint2*)(As + (wm * 32 + gid) * PA1 + 2 * t4);
    const uint2* Bp = (const uint2*)(Ws + (wn * 32 + gid) * PA1 + 2 * t4);

    for (int t = 0; t < TILES1; ++t) {
        if (t) __syncthreads();
        int row0 = (lb0 + t) * 128;
        {
            int r = tid >> 2, lw = tid & 3;
            int rg = row0 + r;
            int m  = rg >> nsShift;
            int p  = idx[rg];
            unsigned* grow = As + r * PA1;
            if (p < 0) {
#pragma unroll
                for (int c = lw * 18; c < lw * 18 + 18; ++c) grow[c] = 0u;
            } else {
                int gp = ((m >> 11) << 13) + p;
                if (lw == 0) {
                    grow[0] = f2tf(xyz[gp * 3 + 0] - newxyz[m * 3 + 0]);
                    grow[2] = f2tf(xyz[gp * 3 + 1] - newxyz[m * 3 + 1]);
                    grow[4] = f2tf(xyz[gp * 3 + 2] - newxyz[m * 3 + 2]);
                }
                const float4* frow = (const float4*)(feat + (size_t)gp * 64);
#pragma unroll
                for (int j = 0; j < 4; ++j) {
                    int f = lw + 4 * j;
                    float4 v = frow[f];
                    grow[slotf(3 + 4 * f + 0)] = f2tf(v.x);
                    grow[slotf(3 + 4 * f + 1)] = f2tf(v.y);
                    grow[slotf(3 + 4 * f + 2)] = f2tf(v.z);
                    grow[slotf(3 + 4 * f + 3)] = f2tf(v.w);
                }
                if (lw == 3) {
                    grow[70] = 0u; grow[65] = 0u; grow[67] = 0u;
                    grow[69] = 0u; grow[71] = 0u;
                }
            }
        }
        __syncthreads();

        float acc[2][4][4];
#pragma unroll
        for (int mt = 0; mt < 2; ++mt)
#pragma unroll
            for (int nt = 0; nt < 4; ++nt)
#pragma unroll
                for (int j = 0; j < 4; ++j) acc[mt][nt][j] = 0.0f;

#pragma unroll
        for (int ks = 0; ks < KS1; ++ks) {
            uint2 a0 = Ap[ks * 4];
            uint2 a1 = Ap[8 * (PA1 / 2) + ks * 4];
            uint2 a2 = Ap[8 * PA1 + ks * 4];
            uint2 a3 = Ap[8 * PA1 + 8 * (PA1 / 2) + ks * 4];
#pragma unroll
            for (int nt = 0; nt < 4; ++nt) {
                uint2 b = Bp[nt * 4 * PA1 + ks * 4];
                mma_tf32(acc[0][nt], a0.x, a1.x, a0.y, a1.y, b.x, b.y);
                mma_tf32(acc[1][nt], a2.x, a3.x, a2.y, a3.y, b.x, b.y);
            }
        }

#pragma unroll
        for (int mt = 0; mt < 2; ++mt) {
            int rbase = row0 + wm * 32 + mt * 16 + gid;
#pragma unroll
            for (int nt = 0; nt < 4; ++nt) {
                int cc = wn * 32 + nt * 8 + t4 * 2;
                *(float2*)(X0 + (size_t)rbase * 128 + cc) =
                    make_float2(acc[mt][nt][0], acc[mt][nt][1]);
                *(float2*)(X0 + (size_t)(rbase + 8) * 128 + cc) =
                    make_float2(acc[mt][nt][2], acc[mt][nt][3]);
            }
        }
#pragma unroll
        for (int nt = 0; nt < 4; ++nt) {
#pragma unroll
            for (int j = 0; j < 2; ++j) {
                float v0 = acc[0][nt][j], v1 = acc[0][nt][j + 2];
                float v2 = acc[1][nt][j], v3 = acc[1][nt][j + 2];
                float s = v0 + v1 + v2 + v3;
                float q = v0 * v0 + v1 * v1 + v2 * v2 + v3 * v3;
#pragma unroll
                for (int o = 4; o <= 16; o <<= 1) {
                    s += __shfl_xor_sync(0xFFFFFFFFu, s, o);
                    q += __shfl_xor_sync(0xFFFFFFFFu, q, o);
                }
                if (gid == 0) {
                    int c = wn * 32 + nt * 8 + t4 * 2 + j;
                    atomicAdd(&s_sum[c], s);
                    atomicAdd(&s_sq[c], q);
                }
            }
        }
    }
    __syncthreads();
    if (tid < 128) {
        atomicAdd(&sum_out[tid], s_sum[tid]);
        atomicAdd(&sq_out[tid], s_sq[tid]);
    }
}

// ---------------------------------------------------------------------------
// GEMM2 (per-scale): block 128x128, 2 row-tiles per block; W + sc/sf staged
// once. A tile register-prefetched: tile0 LDGs issue before W staging (W
// staging hides them); tile t+1 LDGs issue right after the STS sync and ride
// under tile t's mainloop+epilogue. No min-blocks bound: ~100 regs OK (smem
// limits to 1 CTA regardless). X1 stays in registers: raw max/min + stats.
// ---------------------------------------------------------------------------
#define PA2 132
#define PW2 136
#define KS2 16
#define TILES2 2
#define SMEM2B ((128 * PA2 + 128 * PW2 + 512) * 4)

template <int NS>
__global__ __launch_bounds__(512) void gemm2_tc(
    const float* __restrict__ Xin, const float* __restrict__ w1,
    const float* __restrict__ gamma, const float* __restrict__ beta,
    float invR, const float* __restrict__ sum_in,
    const float* __restrict__ sq_in, float* __restrict__ sum_out,
    float* __restrict__ sq_out, float* __restrict__ mxp,
    float* __restrict__ mnp) {
    extern __shared__ unsigned sh[];
    unsigned* As = sh;               // [128][132]
    unsigned* Ws = sh + 128 * PA2;   // [128][136] paired
    float* s_sum = (float*)(sh + 128 * PA2 + 128 * PW2);
    float* s_sq  = s_sum + 128;
    float* sc    = s_sq + 128;
    float* sf    = sc + 128;
    int tid = threadIdx.x;
    int lb0 = blockIdx.x * TILES2;

    // ---- issue tile-0 A loads (registers); W staging below hides them ----
    float4 pf[8];
#pragma unroll
    for (int it = 0; it < 8; ++it) {
        int i = tid + it * 512;
        int r = i >> 5, kq = (i & 31) << 2;
        pf[it] =
            *(const float4*)(Xin + (size_t)(lb0 * 128 + r) * 128 + kq);
    }

    if (tid < 128) {
        s_sum[tid] = 0.0f;
        s_sq[tid]  = 0.0f;
        float mean = sum_in[tid] * invR;
        float var  = sq_in[tid] * invR - mean * mean;
        float s    = gamma[tid] * rsqrtf(var + 1e-5f);
        sc[tid] = s;
        sf[tid] = fmaf(-mean, s, beta[tid]);
    }
    // stage W in paired layout via conflict-free STS.64
    for (int i = tid; i < 128 * 64; i += 512) {
        int o = i >> 6, p = i & 63;
        int c = ((p >> 2) << 3) + (p & 3);
        uint2 u;
        u.x = f2tf(w1[o * 128 + c]);
        u.y = f2tf(w1[o * 128 + c + 4]);
        *(uint2*)(Ws + o * PW2 + ((p >> 2) << 3) + 2 * (p & 3)) = u;
    }
    __syncthreads();

    int lane = tid & 31, wid = tid >> 5;
    int wm = wid & 3, wn = wid >> 2;
    int gid = lane >> 2, t4 = lane & 3;
    const unsigned* Ab = As + (wm * 32 + gid) * PA2 + t4;
    const uint2* Bp = (const uint2*)(Ws + (wn * 32 + gid) * PW2 + 2 * t4);

    for (int t = 0; t < TILES2; ++t) {
        // ---- BN + ReLU + cvt + STS from prefetch registers ----
#pragma unroll
        for (int it = 0; it < 8; ++it) {
            int i = tid + it * 512;
            int r = i >> 5, kq = (i & 31) << 2;
            float4 v = pf[it];
            uint4 uu;
            uu.x = f2tf(fmaxf(fmaf(sc[kq + 0], v.x, sf[kq + 0]), 0.0f));
            uu.y = f2tf(fmaxf(fmaf(sc[kq + 1], v.y, sf[kq + 1]), 0.0f));
            uu.z = f2tf(fmaxf(fmaf(sc[kq + 2], v.z, sf[kq + 2]), 0.0f));
            uu.w = f2tf(fmaxf(fmaf(sc[kq + 3], v.w, sf[kq + 3]), 0.0f));
            *(uint4*)(As + r * PA2 + kq) = uu;
        }
        __syncthreads();

        // ---- issue next tile's A loads; they ride under this mainloop ----
        if (t + 1 < TILES2) {
#pragma unroll
            for (int it = 0; it < 8; ++it) {
                int i = tid + it * 512;
                int r = i >> 5, kq = (i & 31) << 2;
                pf[it] = *(const float4*)(
                    Xin + (size_t)((lb0 + t + 1) * 128 + r) * 128 + kq);
            }
        }

        float acc[2][4][4];
#pragma unroll
        for (int mt = 0; mt < 2; ++mt)
#pragma unroll
            for (int nt = 0; nt < 4; ++nt)
#pragma unroll
                for (int j = 0; j < 4; ++j) acc[mt][nt][j] = 0.0f;

#pragma unroll
        for (int ks = 0; ks < KS2; ++ks) {
            int k0 = ks * 8;
            unsigned a[2][4];
#pragma unroll
            for (int mt = 0; mt < 2; ++mt) {
                const unsigned* ap = Ab + mt * 16 * PA2 + k0;
                a[mt][0] = ap[0];
                a[mt][1] = ap[8 * PA2];
                a[mt][2] = ap[4];
                a[mt][3] = ap[8 * PA2 + 4];
            }
#pragma unroll
            for (int nt = 0; nt < 4; ++nt) {
                uint2 b = Bp[nt * 4 * PW2 + ks * 4];
                mma_tf32(acc[0][nt], a[0][0], a[0][1], a[0][2], a[0][3], b.x,
                         b.y);
                mma_tf32(acc[1][nt], a[1][0], a[1][1], a[1][2], a[1][3], b.x,
                         b.y);
            }
        }

        // ---- fused pooling + stats ----
#pragma unroll
        for (int nt = 0; nt < 4; ++nt) {
#pragma unroll
            for (int j = 0; j < 2; ++j) {
                int c = wn * 32 + nt * 8 + t4 * 2 + j;
                if (NS == 16) {
#pragma unroll
                    for (int mt = 0; mt < 2; ++mt) {
                        float mx = fmaxf(acc[mt][nt][j], acc[mt][nt][j + 2]);
                        float mn = fminf(acc[mt][nt][j], acc[mt][nt][j + 2]);
#pragma unroll
                        for (int o = 4; o <= 16; o <<= 1) {
                            mx = fmaxf(mx,
                                       __shfl_xor_sync(0xFFFFFFFFu, mx, o));
                            mn = fminf(mn,
                                       __shfl_xor_sync(0xFFFFFFFFu, mn, o));
                        }
                        if (gid == 0) {
                            int mq = (lb0 + t) * 8 + wm * 2 + mt;
                            mxp[mq * 128 + c] = mx;
                            mnp[mq * 128 + c] = mn;
                        }
                    }
                } else {
                    float mx = fmaxf(fmaxf(acc[0][nt][j], acc[0][nt][j + 2]),
                                     fmaxf(acc[1][nt][j], acc[1][nt][j + 2]));
                    float mn = fminf(fminf(acc[0][nt][j], acc[0][nt][j + 2]),
                                     fminf(acc[1][nt][j], acc[1][nt][j + 2]));
#pragma unroll
                    for (int o = 4; o <= 16; o <<= 1) {
                        mx = fmaxf(mx, __shfl_xor_sync(0xFFFFFFFFu, mx, o));
                        mn = fminf(mn, __shfl_xor_sync(0xFFFFFFFFu, mn, o));
                    }
                    if (gid == 0) {
                        int mq = (lb0 + t) * 4 + wm;
                        mxp[mq * 128 + c] = mx;
                        mnp[mq * 128 + c] = mn;
                    }
                }
                float v0 = acc[0][nt][j], v1 = acc[0][nt][j + 2];
                float v2 = acc[1][nt][j], v3 = acc[1][nt][j + 2];
                float s = v0 + v1 + v2 + v3;
                float q = v0 * v0 + v1 * v1 + v2 * v2 + v3 * v3;
#pragma unroll
                for (int o = 4; o <= 16; o <<= 1) {
                    s += __shfl_xor_sync(0xFFFFFFFFu, s, o);
                    q += __shfl_xor_sync(0xFFFFFFFFu, q, o);
                }
                if (gid == 0) {
                    atomicAdd(&s_sum[c], s);
                    atomicAdd(&s_sq[c], q);
                }
            }
        }
        if (t + 1 < TILES2) __syncthreads();
    }
    __syncthreads();
    if (tid < 128) {
        atomicAdd(&sum_out[tid], s_sum[tid]);
        atomicAdd(&sq_out[tid], s_sq[tid]);
    }
}

// ---------------------------------------------------------------------------
// Final: BN finalize inline on pooled raw values; pick max/min by sign(s).
// ---------------------------------------------------------------------------
__global__ void poolout(float* __restrict__ out, const float* __restrict__ g01,
                        const float* __restrict__ b01,
                        const float* __restrict__ g11,
                        const float* __restrict__ b11, float invR0,
                        float invR1) {
    int t = blockIdx.x * blockDim.x + threadIdx.x;
    int scl = t >= MTOT * 128;
    int tt = t - scl * MTOT * 128;
    int m = tt >> 7;
    int c = tt & 127;
    const float* sum_in = g_sumA + (scl ? 384 : 128);
    const float* sq_in  = g_sqA + (scl ? 384 : 128);
    const float* gamma = scl ? g11 : g01;
    const float* beta  = scl ? b11 : b01;
    float invR = scl ? invR1 : invR0;

    float mean = sum_in[c] * invR;
    float var  = sq_in[c] * invR - mean * mean;
    float s    = gamma[c] * rsqrtf(var + 1e-5f);
    float b    = fmaf(-mean, s, beta[c]);
    float mx = (scl ? g_mx1 : g_mx0)[tt];
    float mn = (scl ? g_mn1 : g_mn0)[tt];
    float v = (s >= 0.0f) ? mx : mn;
    out[(size_t)m * 256 + (scl ? 128 : 0) + c] = fmaxf(fmaf(s, v, b), 0.0f);
}

// ---------------------------------------------------------------------------
extern "C" void kernel_launch(void* const* d_in, const int* in_sizes, int n_in,
                              void* d_out, int out_size) {
    const float* xyz  = (const float*)d_in[0];
    const float* feat = (const float*)d_in[1];
    const float* nxyz = (const float*)d_in[2];
    const float* w00 = (const float*)d_in[5];
    const float* g00 = (const float*)d_in[6];
    const float* b00 = (const float*)d_in[7];
    const float* w01 = (const float*)d_in[8];
    const float* g01 = (const float*)d_in[9];
    const float* b01 = (const float*)d_in[10];
    const float* w10 = (const float*)d_in[11];
    const float* g10 = (const float*)d_in[12];
    const float* b10 = (const float*)d_in[13];
    const float* w11 = (const float*)d_in[14];
    const float* g11 = (const float*)d_in[15];
    const float* b11 = (const float*)d_in[16];

    float* outBase = (float*)d_out;
    int featOff = out_size - MTOT * 256;
    if (featOff < 0) featOff = 0;
    float* outF = outBase + featOff;

    cudaFuncSetAttribute(gemm1_merged,
                         cudaFuncAttributeMaxDynamicSharedMemorySize, SMEM1B);
    cudaFuncSetAttribute(gemm2_tc<16>,
                         cudaFuncAttributeMaxDynamicSharedMemorySize, SMEM2B);
    cudaFuncSetAttribute(gemm2_tc<32>,
                         cudaFuncAttributeMaxDynamicSharedMemorySize, SMEM2B);

    float* X0a;
    float* X0b;
    float* sumA;
    float* sqA;
    float* mx0;
    float* mn0;
    float* mx1;
    float* mn1;
    cudaGetSymbolAddress((void**)&X0a, g_X0a);
    cudaGetSymbolAddress((void**)&X0b, g_X0b);
    cudaGetSymbolAddress((void**)&sumA, g_sumA);
    cudaGetSymbolAddress((void**)&sqA, g_sqA);
    cudaGetSymbolAddress((void**)&mx0, g_mx0);
    cudaGetSymbolAddress((void**)&mn0, g_mn0);
    cudaGetSymbolAddress((void**)&mx1, g_mx1);
    cudaGetSymbolAddress((void**)&mn1, g_mn1);

    const float r2_0 = (float)(0.2 * 0.2);
    const float r2_1 = (float)(0.4 * 0.4);
    const float invR0 = 1.0f / 131072.0f;
    const float invR1 = 1.0f / 262144.0f;

    ballquery_merged<<<2048, 256>>>(xyz, nxyz, r2_0, r2_1, nxyz, outBase,
                                    featOff);
    gemm1_merged<<<1536, 512, SMEM1B>>>(xyz, feat, nxyz, w00, w10);
    // scale 1 first: gemm1's last-written X0b tail is still L2-resident
    gemm2_tc<32><<<1024, 512, SMEM2B>>>(X0b, w11, g10, b10, invR1, sumA + 256,
                                        sqA + 256, sumA + 384, sqA + 384, mx1,
                                        mn1);
    gemm2_tc<16><<<512, 512, SMEM2B>>>(X0a, w01, g00, b00, invR0, sumA + 0,
                                       sqA + 0, sumA + 128, sqA + 128, mx0,
                                       mn0);
    poolout<<<2 * MTOT * 128 / 256, 256>>>(outF, g01, b01, g11, b11, invR0,
                                           invR1);
}

// round 14
// speedup vs baseline: 1.2434x; 1.0327x over previous
#include <cuda_runtime.h>
#include <cstddef>

// ---------------------------------------------------------------------------
// StackSAModuleMSG — tf32 tensor cores; gemm2 now 1024 threads (32 warps/SM
// in its single resident CTA). X1 never touches DRAM (fused raw max/min).
// B=4, NB=8192, MB=2048, M=8192, C_IN=64, CIN=67 (K padded to 72).
// Scale 0: r=0.2, NS=16 (R=131072).  Scale 1: r=0.4, NS=32 (R=262144).
// ---------------------------------------------------------------------------

#define MTOT 8192
#define NPB  8192

__device__ float g_X0a[131072 * 128];
__device__ float g_X0b[262144 * 128];
__device__ int   g_idx0[8192 * 16];
__device__ int   g_idx1[8192 * 32];
__device__ float g_mx0[8192 * 128];
__device__ float g_mn0[8192 * 128];
__device__ float g_mx1[8192 * 128];
__device__ float g_mn1[8192 * 128];
__device__ float g_sumA[512];   // slots: 0=g1/s0, 1=g2/s0, 2=g1/s1, 3=g2/s1
__device__ float g_sqA[512];

__device__ __forceinline__ unsigned f2tf(float f) {
    unsigned r;
    asm("cvt.rna.tf32.f32 %0, %1;" : "=r"(r) : "f"(f));
    return r;
}

__device__ __forceinline__ int slotf(int c) {
    return (c & ~7) + ((c & 3) * 2) + ((c >> 2) & 1);
}

__device__ __forceinline__ void mma_tf32(float* c, unsigned a0, unsigned a1,
                                         unsigned a2, unsigned a3, unsigned b0,
                                         unsigned b1) {
    asm volatile(
        "mma.sync.aligned.m16n8k8.row.col.f32.tf32.tf32.f32 "
        "{%0,%1,%2,%3}, {%4,%5,%6,%7}, {%8,%9}, {%0,%1,%2,%3};"
        : "+f"(c[0]), "+f"(c[1]), "+f"(c[2]), "+f"(c[3])
        : "r"(a0), "r"(a1), "r"(a2), "r"(a3), "r"(b0), "r"(b1));
}

// ---------------------------------------------------------------------------
// Merged ball query (exact fp32; folds stats zeroing + new_xyz copy).
// ---------------------------------------------------------------------------
__global__ void ballquery_merged(const float* __restrict__ xyz,
                                 const float* __restrict__ newxyz,
                                 float r2_0, float r2_1,
                                 const float* __restrict__ copySrc,
                                 float* __restrict__ copyDst, int copyN) {
    int tid = threadIdx.x;
    if (blockIdx.x == 0) {
        g_sumA[tid] = 0.0f; g_sumA[tid + 256] = 0.0f;
        g_sqA[tid]  = 0.0f; g_sqA[tid + 256]  = 0.0f;
    }
    int ct = blockIdx.x * 256 + tid;
    if (ct < copyN) copyDst[ct] = copySrc[ct];

    int gw   = (blockIdx.x * 256 + tid) >> 5;
    int lane = tid & 31;
    if (gw >= 2 * MTOT) return;
    int scl = gw >> 13;
    int q   = gw & (MTOT - 1);
    int NS  = scl ? 32 : 16;
    float r2 = scl ? r2_1 : r2_0;
    int* idx_out = (scl ? g_idx1 : g_idx0) + q * NS;

    int b = q >> 11;
    float qx = newxyz[q * 3 + 0];
    float qy = newxyz[q * 3 + 1];
    float qz = newxyz[q * 3 + 2];
    float qq = __fadd_rn(__fadd_rn(__fmul_rn(qx, qx), __fmul_rn(qy, qy)),
                         __fmul_rn(qz, qz));
    const float* P = xyz + (size_t)b * NPB * 3;
    int cnt = 0, first = -1;
    for (int start = 0; start < NPB; start += 32) {
        int i = start + lane;
        float px = P[i * 3 + 0];
        float py = P[i * 3 + 1];
        float pz = P[i * 3 + 2];
        float pp = __fadd_rn(__fadd_rn(__fmul_rn(px, px), __fmul_rn(py, py)),
                             __fmul_rn(pz, pz));
        float dt = __fadd_rn(__fadd_rn(__fmul_rn(qx, px), __fmul_rn(qy, py)),
                             __fmul_rn(qz, pz));
        float d2 = __fsub_rn(__fadd_rn(qq, pp), __fmul_rn(2.0f, dt));
        bool in = d2 < r2;
        unsigned mask = __ballot_sync(0xFFFFFFFFu, in);
        if (mask) {
            if (first < 0) first = start + (__ffs(mask) - 1);
            int pos = cnt + __popc(mask & ((1u << lane) - 1u));
            if (in && pos < NS) idx_out[pos] = i;
            cnt += __popc(mask);
            if (cnt >= NS) break;
        }
    }
    if (cnt == 0) {
        for (int j = lane; j < NS; j += 32) idx_out[j] = -1;
    } else if (cnt < NS) {
        for (int j = cnt + lane; j < NS; j += 32) idx_out[j] = first;
    }
}

// ---------------------------------------------------------------------------
// GEMM1: X0[R,128] = gather(G)[R,67] @ W0^T. 512 thr, 16 warps (4m x 4n),
// warp 32x32, block 128x128, 2 row-tiles per block (W staged once).
// Paired-column layout, pitch 72: frag pair = 1 LDS.64.  (unchanged R12)
// ---------------------------------------------------------------------------
#define PA1 72
#define KS1 9
#define TILES1 2
#define SMEM1B ((128 * PA1 * 2 + 256) * 4)

__global__ __launch_bounds__(512, 2) void gemm1_merged(
    const float* __restrict__ xyz, const float* __restrict__ feat,
    const float* __restrict__ newxyz, const float* __restrict__ w00,
    const float* __restrict__ w10) {
    extern __shared__ unsigned sh[];
    unsigned* As = sh;              // [128][72] paired
    unsigned* Ws = sh + 128 * PA1;  // [128][72] paired (W[o][c])
    float* s_sum = (float*)(sh + 2 * 128 * PA1);
    float* s_sq  = s_sum + 128;
    int tid = threadIdx.x;
    int bid = blockIdx.x;
    int scl = bid >= 512;
    int lb0 = (scl ? bid - 512 : bid) * TILES1;
    int nsShift = scl ? 5 : 4;
    const int* idx = scl ? g_idx1 : g_idx0;
    const float* w0 = scl ? w10 : w00;
    float* X0 = scl ? g_X0b : g_X0a;
    float* sum_out = g_sumA + (scl ? 256 : 0);
    float* sq_out  = g_sqA + (scl ? 256 : 0);

    if (tid < 128) { s_sum[tid] = 0.0f; s_sq[tid] = 0.0f; }
    for (int i = tid; i < 128 * PA1; i += 512) {
        int o = i / PA1;
        int c = i - o * PA1;
        Ws[o * PA1 + slotf(c)] = (c < 67) ? f2tf(w0[o * 67 + c]) : 0u;
    }

    int lane = tid & 31, wid = tid >> 5;
    int wm = wid & 3, wn = wid >> 2;
    int gid = lane >> 2, t4 = lane & 3;
    const uint2* Ap = (const uint2*)(As + (wm * 32 + gid) * PA1 + 2 * t4);
    const uint2* Bp = (const uint2*)(Ws + (wn * 32 + gid) * PA1 + 2 * t4);

    for (int t = 0; t < TILES1; ++t) {
        if (t) __syncthreads();
        int row0 = (lb0 + t) * 128;
        {
            int r = tid >> 2, lw = tid & 3;
            int rg = row0 + r;
            int m  = rg >> nsShift;
            int p  = idx[rg];
            unsigned* grow = As + r * PA1;
            if (p < 0) {
#pragma unroll
                for (int c = lw * 18; c < lw * 18 + 18; ++c) grow[c] = 0u;
            } else {
                int gp = ((m >> 11) << 13) + p;
                if (lw == 0) {
                    grow[0] = f2tf(xyz[gp * 3 + 0] - newxyz[m * 3 + 0]);
                    grow[2] = f2tf(xyz[gp * 3 + 1] - newxyz[m * 3 + 1]);
                    grow[4] = f2tf(xyz[gp * 3 + 2] - newxyz[m * 3 + 2]);
                }
                const float4* frow = (const float4*)(feat + (size_t)gp * 64);
#pragma unroll
                for (int j = 0; j < 4; ++j) {
                    int f = lw + 4 * j;
                    float4 v = frow[f];
                    grow[slotf(3 + 4 * f + 0)] = f2tf(v.x);
                    grow[slotf(3 + 4 * f + 1)] = f2tf(v.y);
                    grow[slotf(3 + 4 * f + 2)] = f2tf(v.z);
                    grow[slotf(3 + 4 * f + 3)] = f2tf(v.w);
                }
                if (lw == 3) {
                    grow[70] = 0u; grow[65] = 0u; grow[67] = 0u;
                    grow[69] = 0u; grow[71] = 0u;
                }
            }
        }
        __syncthreads();

        float acc[2][4][4];
#pragma unroll
        for (int mt = 0; mt < 2; ++mt)
#pragma unroll
            for (int nt = 0; nt < 4; ++nt)
#pragma unroll
                for (int j = 0; j < 4; ++j) acc[mt][nt][j] = 0.0f;

#pragma unroll
        for (int ks = 0; ks < KS1; ++ks) {
            uint2 a0 = Ap[ks * 4];
            uint2 a1 = Ap[8 * (PA1 / 2) + ks * 4];
            uint2 a2 = Ap[8 * PA1 + ks * 4];
            uint2 a3 = Ap[8 * PA1 + 8 * (PA1 / 2) + ks * 4];
#pragma unroll
            for (int nt = 0; nt < 4; ++nt) {
                uint2 b = Bp[nt * 4 * PA1 + ks * 4];
                mma_tf32(acc[0][nt], a0.x, a1.x, a0.y, a1.y, b.x, b.y);
                mma_tf32(acc[1][nt], a2.x, a3.x, a2.y, a3.y, b.x, b.y);
            }
        }

#pragma unroll
        for (int mt = 0; mt < 2; ++mt) {
            int rbase = row0 + wm * 32 + mt * 16 + gid;
#pragma unroll
            for (int nt = 0; nt < 4; ++nt) {
                int cc = wn * 32 + nt * 8 + t4 * 2;
                *(float2*)(X0 + (size_t)rbase * 128 + cc) =
                    make_float2(acc[mt][nt][0], acc[mt][nt][1]);
                *(float2*)(X0 + (size_t)(rbase + 8) * 128 + cc) =
                    make_float2(acc[mt][nt][2], acc[mt][nt][3]);
            }
        }
#pragma unroll
        for (int nt = 0; nt < 4; ++nt) {
#pragma unroll
            for (int j = 0; j < 2; ++j) {
                float v0 = acc[0][nt][j], v1 = acc[0][nt][j + 2];
                float v2 = acc[1][nt][j], v3 = acc[1][nt][j + 2];
                float s = v0 + v1 + v2 + v3;
                float q = v0 * v0 + v1 * v1 + v2 * v2 + v3 * v3;
#pragma unroll
                for (int o = 4; o <= 16; o <<= 1) {
                    s += __shfl_xor_sync(0xFFFFFFFFu, s, o);
                    q += __shfl_xor_sync(0xFFFFFFFFu, q, o);
                }
                if (gid == 0) {
                    int c = wn * 32 + nt * 8 + t4 * 2 + j;
                    atomicAdd(&s_sum[c], s);
                    atomicAdd(&s_sq[c], q);
                }
            }
        }
    }
    __syncthreads();
    if (tid < 128) {
        atomicAdd(&sum_out[tid], s_sum[tid]);
        atomicAdd(&sq_out[tid], s_sq[tid]);
    }
}

// ---------------------------------------------------------------------------
// GEMM2 (per-scale): 1024 threads, 32 warps (4m x 8n), warp tile 32x16,
// block 128x128, 2 row-tiles per block; W + sc/sf staged once. A tile
// register-prefetched (tile0 under W staging; tile t+1 under mainloop).
// X1 stays in registers: raw max/min pooling + stats fused; no X1 store.
// ---------------------------------------------------------------------------
#define PA2 132
#define PW2 136
#define KS2 16
#define TILES2 2
#define SMEM2B ((128 * PA2 + 128 * PW2 + 512) * 4)

template <int NS>
__global__ __launch_bounds__(1024) void gemm2_tc(
    const float* __restrict__ Xin, const float* __restrict__ w1,
    const float* __restrict__ gamma, const float* __restrict__ beta,
    float invR, const float* __restrict__ sum_in,
    const float* __restrict__ sq_in, float* __restrict__ sum_out,
    float* __restrict__ sq_out, float* __restrict__ mxp,
    float* __restrict__ mnp) {
    extern __shared__ unsigned sh[];
    unsigned* As = sh;               // [128][132]
    unsigned* Ws = sh + 128 * PA2;   // [128][136] paired
    float* s_sum = (float*)(sh + 128 * PA2 + 128 * PW2);
    float* s_sq  = s_sum + 128;
    float* sc    = s_sq + 128;
    float* sf    = sc + 128;
    int tid = threadIdx.x;
    int lb0 = blockIdx.x * TILES2;

    // ---- issue tile-0 A loads (registers); W staging below hides them ----
    float4 pf[4];
#pragma unroll
    for (int it = 0; it < 4; ++it) {
        int i = tid + it * 1024;
        int r = i >> 5, kq = (i & 31) << 2;
        pf[it] =
            *(const float4*)(Xin + (size_t)(lb0 * 128 + r) * 128 + kq);
    }

    if (tid < 128) {
        s_sum[tid] = 0.0f;
        s_sq[tid]  = 0.0f;
        float mean = sum_in[tid] * invR;
        float var  = sq_in[tid] * invR - mean * mean;
        float s    = gamma[tid] * rsqrtf(var + 1e-5f);
        sc[tid] = s;
        sf[tid] = fmaf(-mean, s, beta[tid]);
    }
    // stage W in paired layout via conflict-free STS.64
    for (int i = tid; i < 128 * 64; i += 1024) {
        int o = i >> 6, p = i & 63;
        int c = ((p >> 2) << 3) + (p & 3);
        uint2 u;
        u.x = f2tf(w1[o * 128 + c]);
        u.y = f2tf(w1[o * 128 + c + 4]);
        *(uint2*)(Ws + o * PW2 + ((p >> 2) << 3) + 2 * (p & 3)) = u;
    }
    __syncthreads();

    int lane = tid & 31, wid = tid >> 5;
    int wm = wid & 3, wn = wid >> 2;       // wm 0..3 (32 rows), wn 0..7 (16 cols)
    int gid = lane >> 2, t4 = lane & 3;
    const unsigned* Ab = As + (wm * 32 + gid) * PA2 + t4;
    const uint2* Bp = (const uint2*)(Ws + (wn * 16 + gid) * PW2 + 2 * t4);

    for (int t = 0; t < TILES2; ++t) {
        // ---- BN + ReLU + cvt + STS from prefetch registers ----
#pragma unroll
        for (int it = 0; it < 4; ++it) {
            int i = tid + it * 1024;
            int r = i >> 5, kq = (i & 31) << 2;
            float4 v = pf[it];
            uint4 uu;
            uu.x = f2tf(fmaxf(fmaf(sc[kq + 0], v.x, sf[kq + 0]), 0.0f));
            uu.y = f2tf(fmaxf(fmaf(sc[kq + 1], v.y, sf[kq + 1]), 0.0f));
            uu.z = f2tf(fmaxf(fmaf(sc[kq + 2], v.z, sf[kq + 2]), 0.0f));
            uu.w = f2tf(fmaxf(fmaf(sc[kq + 3], v.w, sf[kq + 3]), 0.0f));
            *(uint4*)(As + r * PA2 + kq) = uu;
        }
        __syncthreads();

        // ---- issue next tile's A loads; they ride under this mainloop ----
        if (t + 1 < TILES2) {
#pragma unroll
            for (int it = 0; it < 4; ++it) {
                int i = tid + it * 1024;
                int r = i >> 5, kq = (i & 31) << 2;
                pf[it] = *(const float4*)(
                    Xin + (size_t)((lb0 + t + 1) * 128 + r) * 128 + kq);
            }
        }

        float acc[2][2][4];
#pragma unroll
        for (int mt = 0; mt < 2; ++mt)
#pragma unroll
            for (int nt = 0; nt < 2; ++nt)
#pragma unroll
                for (int j = 0; j < 4; ++j) acc[mt][nt][j] = 0.0f;

#pragma unroll
        for (int ks = 0; ks < KS2; ++ks) {
            int k0 = ks * 8;
            unsigned a[2][4];
#pragma unroll
            for (int mt = 0; mt < 2; ++mt) {
                const unsigned* ap = Ab + mt * 16 * PA2 + k0;
                a[mt][0] = ap[0];
                a[mt][1] = ap[8 * PA2];
                a[mt][2] = ap[4];
                a[mt][3] = ap[8 * PA2 + 4];
            }
#pragma unroll
            for (int nt = 0; nt < 2; ++nt) {
                uint2 b = Bp[nt * 4 * PW2 + ks * 4];
                mma_tf32(acc[0][nt], a[0][0], a[0][1], a[0][2], a[0][3], b.x,
                         b.y);
                mma_tf32(acc[1][nt], a[1][0], a[1][1], a[1][2], a[1][3], b.x,
                         b.y);
            }
        }

        // ---- fused pooling + stats ----
#pragma unroll
        for (int nt = 0; nt < 2; ++nt) {
#pragma unroll
            for (int j = 0; j < 2; ++j) {
                int c = wn * 16 + nt * 8 + t4 * 2 + j;
                if (NS == 16) {
#pragma unroll
                    for (int mt = 0; mt < 2; ++mt) {
                        float mx = fmaxf(acc[mt][nt][j], acc[mt][nt][j + 2]);
                        float mn = fminf(acc[mt][nt][j], acc[mt][nt][j + 2]);
#pragma unroll
                        for (int o = 4; o <= 16; o <<= 1) {
                            mx = fmaxf(mx,
                                       __shfl_xor_sync(0xFFFFFFFFu, mx, o));
                            mn = fminf(mn,
                                       __shfl_xor_sync(0xFFFFFFFFu, mn, o));
                        }
                        if (gid == 0) {
                            int mq = (lb0 + t) * 8 + wm * 2 + mt;
                            mxp[mq * 128 + c] = mx;
                            mnp[mq * 128 + c] = mn;
                        }
                    }
                } else {
                    float mx = fmaxf(fmaxf(acc[0][nt][j], acc[0][nt][j + 2]),
                                     fmaxf(acc[1][nt][j], acc[1][nt][j + 2]));
                    float mn = fminf(fminf(acc[0][nt][j], acc[0][nt][j + 2]),
                                     fminf(acc[1][nt][j], acc[1][nt][j + 2]));
#pragma unroll
                    for (int o = 4; o <= 16; o <<= 1) {
                        mx = fmaxf(mx, __shfl_xor_sync(0xFFFFFFFFu, mx, o));
                        mn = fminf(mn, __shfl_xor_sync(0xFFFFFFFFu, mn, o));
                    }
                    if (gid == 0) {
                        int mq = (lb0 + t) * 4 + wm;
                        mxp[mq * 128 + c] = mx;
                        mnp[mq * 128 + c] = mn;
                    }
                }
                float v0 = acc[0][nt][j], v1 = acc[0][nt][j + 2];
                float v2 = acc[1][nt][j], v3 = acc[1][nt][j + 2];
                float s = v0 + v1 + v2 + v3;
                float q = v0 * v0 + v1 * v1 + v2 * v2 + v3 * v3;
#pragma unroll
                for (int o = 4; o <= 16; o <<= 1) {
                    s += __shfl_xor_sync(0xFFFFFFFFu, s, o);
                    q += __shfl_xor_sync(0xFFFFFFFFu, q, o);
                }
                if (gid == 0) {
                    atomicAdd(&s_sum[c], s);
                    atomicAdd(&s_sq[c], q);
                }
            }
        }
        if (t + 1 < TILES2) __syncthreads();
    }
    __syncthreads();
    if (tid < 128) {
        atomicAdd(&sum_out[tid], s_sum[tid]);
        atomicAdd(&sq_out[tid], s_sq[tid]);
    }
}

// ---------------------------------------------------------------------------
// Final: BN finalize inline on pooled raw values; pick max/min by sign(s).
// ---------------------------------------------------------------------------
__global__ void poolout(float* __restrict__ out, const float* __restrict__ g01,
                        const float* __restrict__ b01,
                        const float* __restrict__ g11,
                        const float* __restrict__ b11, float invR0,
                        float invR1) {
    int t = blockIdx.x * blockDim.x + threadIdx.x;
    int scl = t >= MTOT * 128;
    int tt = t - scl * MTOT * 128;
    int m = tt >> 7;
    int c = tt & 127;
    const float* sum_in = g_sumA + (scl ? 384 : 128);
    const float* sq_in  = g_sqA + (scl ? 384 : 128);
    const float* gamma = scl ? g11 : g01;
    const float* beta  = scl ? b11 : b01;
    float invR = scl ? invR1 : invR0;

    float mean = sum_in[c] * invR;
    float var  = sq_in[c] * invR - mean * mean;
    float s    = gamma[c] * rsqrtf(var + 1e-5f);
    float b    = fmaf(-mean, s, beta[c]);
    float mx = (scl ? g_mx1 : g_mx0)[tt];
    float mn = (scl ? g_mn1 : g_mn0)[tt];
    float v = (s >= 0.0f) ? mx : mn;
    out[(size_t)m * 256 + (scl ? 128 : 0) + c] = fmaxf(fmaf(s, v, b), 0.0f);
}

// ---------------------------------------------------------------------------
extern "C" void kernel_launch(void* const* d_in, const int* in_sizes, int n_in,
                              void* d_out, int out_size) {
    const float* xyz  = (const float*)d_in[0];
    const float* feat = (const float*)d_in[1];
    const float* nxyz = (const float*)d_in[2];
    const float* w00 = (const float*)d_in[5];
    const float* g00 = (const float*)d_in[6];
    const float* b00 = (const float*)d_in[7];
    const float* w01 = (const float*)d_in[8];
    const float* g01 = (const float*)d_in[9];
    const float* b01 = (const float*)d_in[10];
    const float* w10 = (const float*)d_in[11];
    const float* g10 = (const float*)d_in[12];
    const float* b10 = (const float*)d_in[13];
    const float* w11 = (const float*)d_in[14];
    const float* g11 = (const float*)d_in[15];
    const float* b11 = (const float*)d_in[16];

    float* outBase = (float*)d_out;
    int featOff = out_size - MTOT * 256;
    if (featOff < 0) featOff = 0;
    float* outF = outBase + featOff;

    cudaFuncSetAttribute(gemm1_merged,
                         cudaFuncAttributeMaxDynamicSharedMemorySize, SMEM1B);
    cudaFuncSetAttribute(gemm2_tc<16>,
                         cudaFuncAttributeMaxDynamicSharedMemorySize, SMEM2B);
    cudaFuncSetAttribute(gemm2_tc<32>,
                         cudaFuncAttributeMaxDynamicSharedMemorySize, SMEM2B);

    float* X0a;
    float* X0b;
    float* sumA;
    float* sqA;
    float* mx0;
    float* mn0;
    float* mx1;
    float* mn1;
    cudaGetSymbolAddress((void**)&X0a, g_X0a);
    cudaGetSymbolAddress((void**)&X0b, g_X0b);
    cudaGetSymbolAddress((void**)&sumA, g_sumA);
    cudaGetSymbolAddress((void**)&sqA, g_sqA);
    cudaGetSymbolAddress((void**)&mx0, g_mx0);
    cudaGetSymbolAddress((void**)&mn0, g_mn0);
    cudaGetSymbolAddress((void**)&mx1, g_mx1);
    cudaGetSymbolAddress((void**)&mn1, g_mn1);

    const float r2_0 = (float)(0.2 * 0.2);
    const float r2_1 = (float)(0.4 * 0.4);
    const float invR0 = 1.0f / 131072.0f;
    const float invR1 = 1.0f / 262144.0f;

    ballquery_merged<<<2048, 256>>>(xyz, nxyz, r2_0, r2_1, nxyz, outBase,
                                    featOff);
    gemm1_merged<<<1536, 512, SMEM1B>>>(xyz, feat, nxyz, w00, w10);
    // scale 1 first: gemm1's last-written X0b tail is still L2-resident
    gemm2_tc<32><<<1024, 1024, SMEM2B>>>(X0b, w11, g10, b10, invR1,
                                         sumA + 256, sqA + 256, sumA + 384,
                                         sqA + 384, mx1, mn1);
    gemm2_tc<16><<<512, 1024, SMEM2B>>>(X0a, w01, g00, b00, invR0, sumA + 0,
                                        sqA + 0, sumA + 128, sqA + 128, mx0,
                                        mn0);
    poolout<<<2 * MTOT * 128 / 256, 256>>>(outF, g01, b01, g11, b11, invR0,
                                           invR1);
}

// round 15
// speedup vs baseline: 1.4032x; 1.1286x over previous
#include <cuda_runtime.h>
#include <cuda_fp16.h>
#include <cstddef>

// ---------------------------------------------------------------------------
// StackSAModuleMSG — gemm1 tf32, gemm2 fp16 m16n8k16 (fp32 accum).
// X1 never touches DRAM (fused raw max/min pooling in gemm2 registers).
// B=4, NB=8192, MB=2048, M=8192, C_IN=64, CIN=67 (K padded to 72).
// Scale 0: r=0.2, NS=16 (R=131072).  Scale 1: r=0.4, NS=32 (R=262144).
// ---------------------------------------------------------------------------

#define MTOT 8192
#define NPB  8192

__device__ float g_X0a[131072 * 128];
__device__ float g_X0b[262144 * 128];
__device__ int   g_idx0[8192 * 16];
__device__ int   g_idx1[8192 * 32];
__device__ float g_mx0[8192 * 128];
__device__ float g_mn0[8192 * 128];
__device__ float g_mx1[8192 * 128];
__device__ float g_mn1[8192 * 128];
__device__ float g_sumA[512];   // slots: 0=g1/s0, 1=g2/s0, 2=g1/s1, 3=g2/s1
__device__ float g_sqA[512];

__device__ __forceinline__ unsigned f2tf(float f) {
    unsigned r;
    asm("cvt.rna.tf32.f32 %0, %1;" : "=r"(r) : "f"(f));
    return r;
}

__device__ __forceinline__ unsigned pack_h2(float lo, float hi) {
    __half2 h = __floats2half2_rn(lo, hi);
    return *(unsigned*)&h;
}

__device__ __forceinline__ int slotf(int c) {
    return (c & ~7) + ((c & 3) * 2) + ((c >> 2) & 1);
}

__device__ __forceinline__ void mma_tf32(float* c, unsigned a0, unsigned a1,
                                         unsigned a2, unsigned a3, unsigned b0,
                                         unsigned b1) {
    asm volatile(
        "mma.sync.aligned.m16n8k8.row.col.f32.tf32.tf32.f32 "
        "{%0,%1,%2,%3}, {%4,%5,%6,%7}, {%8,%9}, {%0,%1,%2,%3};"
        : "+f"(c[0]), "+f"(c[1]), "+f"(c[2]), "+f"(c[3])
        : "r"(a0), "r"(a1), "r"(a2), "r"(a3), "r"(b0), "r"(b1));
}

__device__ __forceinline__ void mma_f16(float* c, unsigned a0, unsigned a1,
                                        unsigned a2, unsigned a3, unsigned b0,
                                        unsigned b1) {
    asm volatile(
        "mma.sync.aligned.m16n8k16.row.col.f32.f16.f16.f32 "
        "{%0,%1,%2,%3}, {%4,%5,%6,%7}, {%8,%9}, {%0,%1,%2,%3};"
        : "+f"(c[0]), "+f"(c[1]), "+f"(c[2]), "+f"(c[3])
        : "r"(a0), "r"(a1), "r"(a2), "r"(a3), "r"(b0), "r"(b1));
}

// ---------------------------------------------------------------------------
// Merged ball query (exact fp32; folds stats zeroing + new_xyz copy).
// ---------------------------------------------------------------------------
__global__ void ballquery_merged(const float* __restrict__ xyz,
                                 const float* __restrict__ newxyz,
                                 float r2_0, float r2_1,
                                 const float* __restrict__ copySrc,
                                 float* __restrict__ copyDst, int copyN) {
    int tid = threadIdx.x;
    if (blockIdx.x == 0) {
        g_sumA[tid] = 0.0f; g_sumA[tid + 256] = 0.0f;
        g_sqA[tid]  = 0.0f; g_sqA[tid + 256]  = 0.0f;
    }
    int ct = blockIdx.x * 256 + tid;
    if (ct < copyN) copyDst[ct] = copySrc[ct];

    int gw   = (blockIdx.x * 256 + tid) >> 5;
    int lane = tid & 31;
    if (gw >= 2 * MTOT) return;
    int scl = gw >> 13;
    int q   = gw & (MTOT - 1);
    int NS  = scl ? 32 : 16;
    float r2 = scl ? r2_1 : r2_0;
    int* idx_out = (scl ? g_idx1 : g_idx0) + q * NS;

    int b = q >> 11;
    float qx = newxyz[q * 3 + 0];
    float qy = newxyz[q * 3 + 1];
    float qz = newxyz[q * 3 + 2];
    float qq = __fadd_rn(__fadd_rn(__fmul_rn(qx, qx), __fmul_rn(qy, qy)),
                         __fmul_rn(qz, qz));
    const float* P = xyz + (size_t)b * NPB * 3;
    int cnt = 0, first = -1;
    for (int start = 0; start < NPB; start += 32) {
        int i = start + lane;
        float px = P[i * 3 + 0];
        float py = P[i * 3 + 1];
        float pz = P[i * 3 + 2];
        float pp = __fadd_rn(__fadd_rn(__fmul_rn(px, px), __fmul_rn(py, py)),
                             __fmul_rn(pz, pz));
        float dt = __fadd_rn(__fadd_rn(__fmul_rn(qx, px), __fmul_rn(qy, py)),
                             __fmul_rn(qz, pz));
        float d2 = __fsub_rn(__fadd_rn(qq, pp), __fmul_rn(2.0f, dt));
        bool in = d2 < r2;
        unsigned mask = __ballot_sync(0xFFFFFFFFu, in);
        if (mask) {
            if (first < 0) first = start + (__ffs(mask) - 1);
            int pos = cnt + __popc(mask & ((1u << lane) - 1u));
            if (in && pos < NS) idx_out[pos] = i;
            cnt += __popc(mask);
            if (cnt >= NS) break;
        }
    }
    if (cnt == 0) {
        for (int j = lane; j < NS; j += 32) idx_out[j] = -1;
    } else if (cnt < NS) {
        for (int j = cnt + lane; j < NS; j += 32) idx_out[j] = first;
    }
}

// ---------------------------------------------------------------------------
// GEMM1: X0[R,128] = gather(G)[R,67] @ W0^T. 512 thr, 16 warps (4m x 4n),
// warp 32x32, block 128x128, 2 row-tiles per block (W staged once).
// Paired-column tf32 layout, pitch 72: frag pair = 1 LDS.64. (unchanged)
// ---------------------------------------------------------------------------
#define PA1 72
#define KS1 9
#define TILES1 2
#define SMEM1B ((128 * PA1 * 2 + 256) * 4)

__global__ __launch_bounds__(512, 2) void gemm1_merged(
    const float* __restrict__ xyz, const float* __restrict__ feat,
    const float* __restrict__ newxyz, const float* __restrict__ w00,
    const float* __restrict__ w10) {
    extern __shared__ unsigned sh[];
    unsigned* As = sh;              // [128][72] paired
    unsigned* Ws = sh + 128 * PA1;  // [128][72] paired (W[o][c])
    float* s_sum = (float*)(sh + 2 * 128 * PA1);
    float* s_sq  = s_sum + 128;
    int tid = threadIdx.x;
    int bid = blockIdx.x;
    int scl = bid >= 512;
    int lb0 = (scl ? bid - 512 : bid) * TILES1;
    int nsShift = scl ? 5 : 4;
    const int* idx = scl ? g_idx1 : g_idx0;
    const float* w0 = scl ? w10 : w00;
    float* X0 = scl ? g_X0b : g_X0a;
    float* sum_out = g_sumA + (scl ? 256 : 0);
    float* sq_out  = g_sqA + (scl ? 256 : 0);

    if (tid < 128) { s_sum[tid] = 0.0f; s_sq[tid] = 0.0f; }
    for (int i = tid; i < 128 * PA1; i += 512) {
        int o = i / PA1;
        int c = i - o * PA1;
        Ws[o * PA1 + slotf(c)] = (c < 67) ? f2tf(w0[o * 67 + c]) : 0u;
    }

    int lane = tid & 31, wid = tid >> 5;
    int wm = wid & 3, wn = wid >> 2;
    int gid = lane >> 2, t4 = lane & 3;
    const uint2* Ap = (const uint2*)(As + (wm * 32 + gid) * PA1 + 2 * t4);
    const uint2* Bp = (const uint2*)(Ws + (wn * 32 + gid) * PA1 + 2 * t4);

    for (int t = 0; t < TILES1; ++t) {
        if (t) __syncthreads();
        int row0 = (lb0 + t) * 128;
        {
            int r = tid >> 2, lw = tid & 3;
            int rg = row0 + r;
            int m  = rg >> nsShift;
            int p  = idx[rg];
            unsigned* grow = As + r * PA1;
            if (p < 0) {
#pragma unroll
                for (int c = lw * 18; c < lw * 18 + 18; ++c) grow[c] = 0u;
            } else {
                int gp = ((m >> 11) << 13) + p;
                if (lw == 0) {
                    grow[0] = f2tf(xyz[gp * 3 + 0] - newxyz[m * 3 + 0]);
                    grow[2] = f2tf(xyz[gp * 3 + 1] - newxyz[m * 3 + 1]);
                    grow[4] = f2tf(xyz[gp * 3 + 2] - newxyz[m * 3 + 2]);
                }
                const float4* frow = (const float4*)(feat + (size_t)gp * 64);
#pragma unroll
                for (int j = 0; j < 4; ++j) {
                    int f = lw + 4 * j;
                    float4 v = frow[f];
                    grow[slotf(3 + 4 * f + 0)] = f2tf(v.x);
                    grow[slotf(3 + 4 * f + 1)] = f2tf(v.y);
                    grow[slotf(3 + 4 * f + 2)] = f2tf(v.z);
                    grow[slotf(3 + 4 * f + 3)] = f2tf(v.w);
                }
                if (lw == 3) {
                    grow[70] = 0u; grow[65] = 0u; grow[67] = 0u;
                    grow[69] = 0u; grow[71] = 0u;
                }
            }
        }
        __syncthreads();

        float acc[2][4][4];
#pragma unroll
        for (int mt = 0; mt < 2; ++mt)
#pragma unroll
            for (int nt = 0; nt < 4; ++nt)
#pragma unroll
                for (int j = 0; j < 4; ++j) acc[mt][nt][j] = 0.0f;

#pragma unroll
        for (int ks = 0; ks < KS1; ++ks) {
            uint2 a0 = Ap[ks * 4];
            uint2 a1 = Ap[8 * (PA1 / 2) + ks * 4];
            uint2 a2 = Ap[8 * PA1 + ks * 4];
            uint2 a3 = Ap[8 * PA1 + 8 * (PA1 / 2) + ks * 4];
#pragma unroll
            for (int nt = 0; nt < 4; ++nt) {
                uint2 b = Bp[nt * 4 * PA1 + ks * 4];
                mma_tf32(acc[0][nt], a0.x, a1.x, a0.y, a1.y, b.x, b.y);
                mma_tf32(acc[1][nt], a2.x, a3.x, a2.y, a3.y, b.x, b.y);
            }
        }

#pragma unroll
        for (int mt = 0; mt < 2; ++mt) {
            int rbase = row0 + wm * 32 + mt * 16 + gid;
#pragma unroll
            for (int nt = 0; nt < 4; ++nt) {
                int cc = wn * 32 + nt * 8 + t4 * 2;
                *(float2*)(X0 + (size_t)rbase * 128 + cc) =
                    make_float2(acc[mt][nt][0], acc[mt][nt][1]);
                *(float2*)(X0 + (size_t)(rbase + 8) * 128 + cc) =
                    make_float2(acc[mt][nt][2], acc[mt][nt][3]);
            }
        }
#pragma unroll
        for (int nt = 0; nt < 4; ++nt) {
#pragma unroll
            for (int j = 0; j < 2; ++j) {
                float v0 = acc[0][nt][j], v1 = acc[0][nt][j + 2];
                float v2 = acc[1][nt][j], v3 = acc[1][nt][j + 2];
                float s = v0 + v1 + v2 + v3;
                float q = v0 * v0 + v1 * v1 + v2 * v2 + v3 * v3;
#pragma unroll
                for (int o = 4; o <= 16; o <<= 1) {
                    s += __shfl_xor_sync(0xFFFFFFFFu, s, o);
                    q += __shfl_xor_sync(0xFFFFFFFFu, q, o);
                }
                if (gid == 0) {
                    int c = wn * 32 + nt * 8 + t4 * 2 + j;
                    atomicAdd(&s_sum[c], s);
                    atomicAdd(&s_sq[c], q);
                }
            }
        }
    }
    __syncthreads();
    if (tid < 128) {
        atomicAdd(&sum_out[tid], s_sum[tid]);
        atomicAdd(&sq_out[tid], s_sq[tid]);
    }
}

// ---------------------------------------------------------------------------
// GEMM2 (per-scale, fp16): 1024 threads, 32 warps (4m x 8n), warp 32x16,
// block 128x128, 2 row-tiles per block; m16n8k16 f16 MMA, fp32 accum.
// A/W in f16x2 words, 64 words/row, pitch 68 (conflict-free LDS.32 frags).
// A register-prefetched; X1 stays in registers (max/min + stats fused).
// ---------------------------------------------------------------------------
#define PAH 68
#define KSH 8
#define TILES2 2
#define SMEM2H ((128 * PAH * 2 + 512) * 4)

template <int NS>
__global__ __launch_bounds__(1024) void gemm2_tc(
    const float* __restrict__ Xin, const float* __restrict__ w1,
    const float* __restrict__ gamma, const float* __restrict__ beta,
    float invR, const float* __restrict__ sum_in,
    const float* __restrict__ sq_in, float* __restrict__ sum_out,
    float* __restrict__ sq_out, float* __restrict__ mxp,
    float* __restrict__ mnp) {
    extern __shared__ unsigned sh[];
    unsigned* As = sh;               // [128][68] f16x2 words
    unsigned* Ws = sh + 128 * PAH;   // [128][68] f16x2 words
    float* s_sum = (float*)(sh + 2 * 128 * PAH);
    float* s_sq  = s_sum + 128;
    float* sc    = s_sq + 128;
    float* sf    = sc + 128;
    int tid = threadIdx.x;
    int lb0 = blockIdx.x * TILES2;

    // ---- tile-0 A prefetch: 2 groups of 8 cols per thread ----
    // group i: row r = i>>4, kg = i&15; loads cols kg*8..+7 (2x float4)
    float4 pf[4];
#pragma unroll
    for (int it = 0; it < 2; ++it) {
        int i = tid + it * 1024;
        int r = i >> 4, kg = i & 15;
        const float* src = Xin + (size_t)(lb0 * 128 + r) * 128 + kg * 8;
        pf[2 * it]     = *(const float4*)(src);
        pf[2 * it + 1] = *(const float4*)(src + 4);
    }

    if (tid < 128) {
        s_sum[tid] = 0.0f;
        s_sq[tid]  = 0.0f;
        float mean = sum_in[tid] * invR;
        float var  = sq_in[tid] * invR - mean * mean;
        float s    = gamma[tid] * rsqrtf(var + 1e-5f);
        sc[tid] = s;
        sf[tid] = fmaf(-mean, s, beta[tid]);
    }
    // ---- stage W as f16x2: thread handles 8-col groups -> STS.128 ----
    for (int i = tid; i < 128 * 16; i += 1024) {
        int o = i >> 4, kg = i & 15;
        const float* wr = w1 + o * 128 + kg * 8;
        float4 v0 = *(const float4*)(wr);
        float4 v1 = *(const float4*)(wr + 4);
        uint4 u;
        u.x = pack_h2(v0.x, v0.y);
        u.y = pack_h2(v0.z, v0.w);
        u.z = pack_h2(v1.x, v1.y);
        u.w = pack_h2(v1.z, v1.w);
        *(uint4*)(Ws + o * PAH + kg * 4) = u;
    }
    __syncthreads();

    int lane = tid & 31, wid = tid >> 5;
    int wm = wid & 3, wn = wid >> 2;   // wm: 32 rows, wn: 16 cols
    int gid = lane >> 2, t4 = lane & 3;
    const unsigned* Ab = As + (wm * 32 + gid) * PAH + t4;
    const unsigned* Bb = Ws + (wn * 16 + gid) * PAH + t4;

    for (int t = 0; t < TILES2; ++t) {
        // ---- BN + ReLU + f16 pack + STS.128 from prefetch registers ----
#pragma unroll
        for (int it = 0; it < 2; ++it) {
            int i = tid + it * 1024;
            int r = i >> 4, kg = i & 15;
            int kq = kg * 8;
            float4 v0 = pf[2 * it];
            float4 v1 = pf[2 * it + 1];
            float x0 = fmaxf(fmaf(sc[kq + 0], v0.x, sf[kq + 0]), 0.0f);
            float x1 = fmaxf(fmaf(sc[kq + 1], v0.y, sf[kq + 1]), 0.0f);
            float x2 = fmaxf(fmaf(sc[kq + 2], v0.z, sf[kq + 2]), 0.0f);
            float x3 = fmaxf(fmaf(sc[kq + 3], v0.w, sf[kq + 3]), 0.0f);
            float x4 = fmaxf(fmaf(sc[kq + 4], v1.x, sf[kq + 4]), 0.0f);
            float x5 = fmaxf(fmaf(sc[kq + 5], v1.y, sf[kq + 5]), 0.0f);
            float x6 = fmaxf(fmaf(sc[kq + 6], v1.z, sf[kq + 6]), 0.0f);
            float x7 = fmaxf(fmaf(sc[kq + 7], v1.w, sf[kq + 7]), 0.0f);
            uint4 u;
            u.x = pack_h2(x0, x1);
            u.y = pack_h2(x2, x3);
            u.z = pack_h2(x4, x5);
            u.w = pack_h2(x6, x7);
            *(uint4*)(As + r * PAH + kg * 4) = u;
        }
        __syncthreads();

        // ---- next tile's A loads ride under this mainloop ----
        if (t + 1 < TILES2) {
#pragma unroll
            for (int it = 0; it < 2; ++it) {
                int i = tid + it * 1024;
                int r = i >> 4, kg = i & 15;
                const float* src =
                    Xin + (size_t)((lb0 + t + 1) * 128 + r) * 128 + kg * 8;
                pf[2 * it]     = *(const float4*)(src);
                pf[2 * it + 1] = *(const float4*)(src + 4);
            }
        }

        float acc[2][2][4];
#pragma unroll
        for (int mt = 0; mt < 2; ++mt)
#pragma unroll
            for (int nt = 0; nt < 2; ++nt)
#pragma unroll
                for (int j = 0; j < 4; ++j) acc[mt][nt][j] = 0.0f;

#pragma unroll
        for (int ks = 0; ks < KSH; ++ks) {
            int k0 = ks * 8;  // word offset (16 cols = 8 words)
            unsigned a[2][4];
#pragma unroll
            for (int mt = 0; mt < 2; ++mt) {
                const unsigned* ap = Ab + mt * 16 * PAH + k0;
                a[mt][0] = ap[0];
                a[mt][1] = ap[8 * PAH];
                a[mt][2] = ap[4];
                a[mt][3] = ap[8 * PAH + 4];
            }
#pragma unroll
            for (int nt = 0; nt < 2; ++nt) {
                const unsigned* bp = Bb + nt * 8 * PAH + k0;
                unsigned b0 = bp[0], b1 = bp[4];
                mma_f16(acc[0][nt], a[0][0], a[0][1], a[0][2], a[0][3], b0,
                        b1);
                mma_f16(acc[1][nt], a[1][0], a[1][1], a[1][2], a[1][3], b0,
                        b1);
            }
        }

        // ---- fused pooling + stats (same mapping as tf32 version) ----
#pragma unroll
        for (int nt = 0; nt < 2; ++nt) {
#pragma unroll
            for (int j = 0; j < 2; ++j) {
                int c = wn * 16 + nt * 8 + t4 * 2 + j;
                if (NS == 16) {
#pragma unroll
                    for (int mt = 0; mt < 2; ++mt) {
                        float mx = fmaxf(acc[mt][nt][j], acc[mt][nt][j + 2]);
                        float mn = fminf(acc[mt][nt][j], acc[mt][nt][j + 2]);
#pragma unroll
                        for (int o = 4; o <= 16; o <<= 1) {
                            mx = fmaxf(mx,
                                       __shfl_xor_sync(0xFFFFFFFFu, mx, o));
                            mn = fminf(mn,
                                       __shfl_xor_sync(0xFFFFFFFFu, mn, o));
                        }
                        if (gid == 0) {
                            int mq = (lb0 + t) * 8 + wm * 2 + mt;
                            mxp[mq * 128 + c] = mx;
                            mnp[mq * 128 + c] = mn;
                        }
                    }
                } else {
                    float mx = fmaxf(fmaxf(acc[0][nt][j], acc[0][nt][j + 2]),
                                     fmaxf(acc[1][nt][j], acc[1][nt][j + 2]));
                    float mn = fminf(fminf(acc[0][nt][j], acc[0][nt][j + 2]),
                                     fminf(acc[1][nt][j], acc[1][nt][j + 2]));
#pragma unroll
                    for (int o = 4; o <= 16; o <<= 1) {
                        mx = fmaxf(mx, __shfl_xor_sync(0xFFFFFFFFu, mx, o));
                        mn = fminf(mn, __shfl_xor_sync(0xFFFFFFFFu, mn, o));
                    }
                    if (gid == 0) {
                        int mq = (lb0 + t) * 4 + wm;
                        mxp[mq * 128 + c] = mx;
                        mnp[mq * 128 + c] = mn;
                    }
                }
                float v0 = acc[0][nt][j], v1 = acc[0][nt][j + 2];
                float v2 = acc[1][nt][j], v3 = acc[1][nt][j + 2];
                float s = v0 + v1 + v2 + v3;
                float q = v0 * v0 + v1 * v1 + v2 * v2 + v3 * v3;
#pragma unroll
                for (int o = 4; o <= 16; o <<= 1) {
                    s += __shfl_xor_sync(0xFFFFFFFFu, s, o);
                    q += __shfl_xor_sync(0xFFFFFFFFu, q, o);
                }
                if (gid == 0) {
                    atomicAdd(&s_sum[c], s);
                    atomicAdd(&s_sq[c], q);
                }
            }
        }
        if (t + 1 < TILES2) __syncthreads();
    }
    __syncthreads();
    if (tid < 128) {
        atomicAdd(&sum_out[tid], s_sum[tid]);
        atomicAdd(&sq_out[tid], s_sq[tid]);
    }
}

// ---------------------------------------------------------------------------
// Final: BN finalize inline on pooled raw values; pick max/min by sign(s).
// ---------------------------------------------------------------------------
__global__ void poolout(float* __restrict__ out, const float* __restrict__ g01,
                        const float* __restrict__ b01,
                        const float* __restrict__ g11,
                        const float* __restrict__ b11, float invR0,
                        float invR1) {
    int t = blockIdx.x * blockDim.x + threadIdx.x;
    int scl = t >= MTOT * 128;
    int tt = t - scl * MTOT * 128;
    int m = tt >> 7;
    int c = tt & 127;
    const float* sum_in = g_sumA + (scl ? 384 : 128);
    const float* sq_in  = g_sqA + (scl ? 384 : 128);
    const float* gamma = scl ? g11 : g01;
    const float* beta  = scl ? b11 : b01;
    float invR = scl ? invR1 : invR0;

    float mean = sum_in[c] * invR;
    float var  = sq_in[c] * invR - mean * mean;
    float s    = gamma[c] * rsqrtf(var + 1e-5f);
    float b    = fmaf(-mean, s, beta[c]);
    float mx = (scl ? g_mx1 : g_mx0)[tt];
    float mn = (scl ? g_mn1 : g_mn0)[tt];
    float v = (s >= 0.0f) ? mx : mn;
    out[(size_t)m * 256 + (scl ? 128 : 0) + c] = fmaxf(fmaf(s, v, b), 0.0f);
}

// ---------------------------------------------------------------------------
extern "C" void kernel_launch(void* const* d_in, const int* in_sizes, int n_in,
                              void* d_out, int out_size) {
    const float* xyz  = (const float*)d_in[0];
    const float* feat = (const float*)d_in[1];
    const float* nxyz = (const float*)d_in[2];
    const float* w00 = (const float*)d_in[5];
    const float* g00 = (const float*)d_in[6];
    const float* b00 = (const float*)d_in[7];
    const float* w01 = (const float*)d_in[8];
    const float* g01 = (const float*)d_in[9];
    const float* b01 = (const float*)d_in[10];
    const float* w10 = (const float*)d_in[11];
    const float* g10 = (const float*)d_in[12];
    const float* b10 = (const float*)d_in[13];
    const float* w11 = (const float*)d_in[14];
    const float* g11 = (const float*)d_in[15];
    const float* b11 = (const float*)d_in[16];

    float* outBase = (float*)d_out;
    int featOff = out_size - MTOT * 256;
    if (featOff < 0) featOff = 0;
    float* outF = outBase + featOff;

    cudaFuncSetAttribute(gemm1_merged,
                         cudaFuncAttributeMaxDynamicSharedMemorySize, SMEM1B);
    cudaFuncSetAttribute(gemm2_tc<16>,
                         cudaFuncAttributeMaxDynamicSharedMemorySize, SMEM2H);
    cudaFuncSetAttribute(gemm2_tc<32>,
                         cudaFuncAttributeMaxDynamicSharedMemorySize, SMEM2H);

    float* X0a;
    float* X0b;
    float* sumA;
    float* sqA;
    float* mx0;
    float* mn0;
    float* mx1;
    float* mn1;
    cudaGetSymbolAddress((void**)&X0a, g_X0a);
    cudaGetSymbolAddress((void**)&X0b, g_X0b);
    cudaGetSymbolAddress((void**)&sumA, g_sumA);
    cudaGetSymbolAddress((void**)&sqA, g_sqA);
    cudaGetSymbolAddress((void**)&mx0, g_mx0);
    cudaGetSymbolAddress((void**)&mn0, g_mn0);
    cudaGetSymbolAddress((void**)&mx1, g_mx1);
    cudaGetSymbolAddress((void**)&mn1, g_mn1);

    const float r2_0 = (float)(0.2 * 0.2);
    const float r2_1 = (float)(0.4 * 0.4);
    const float invR0 = 1.0f / 131072.0f;
    const float invR1 = 1.0f / 262144.0f;

    ballquery_merged<<<2048, 256>>>(xyz, nxyz, r2_0, r2_1, nxyz, outBase,
                                    featOff);
    gemm1_merged<<<1536, 512, SMEM1B>>>(xyz, feat, nxyz, w00, w10);
    // scale 1 first: gemm1's last-written X0b tail is still L2-resident
    gemm2_tc<32><<<1024, 1024, SMEM2H>>>(X0b, w11, g10, b10, invR1,
                                         sumA + 256, sqA + 256, sumA + 384,
                                         sqA + 384, mx1, mn1);
    gemm2_tc<16><<<512, 1024, SMEM2H>>>(X0a, w01, g00, b00, invR0, sumA + 0,
                                        sqA + 0, sumA + 128, sqA + 128, mx0,
                                        mn0);
    poolout<<<2 * MTOT * 128 / 256, 256>>>(outF, g01, b01, g11, b11, invR0,
                                           invR1);
}

// round 16
// speedup vs baseline: 1.5218x; 1.0845x over previous
#include <cuda_runtime.h>
#include <cuda_fp16.h>
#include <cstddef>

// ---------------------------------------------------------------------------
// StackSAModuleMSG — both GEMMs fp16 m16n8k16 (fp32 accum; fp16 mantissa ==
// tf32 mantissa, so accuracy is unchanged vs tf32 for this value range).
// X1 never touches DRAM (fused raw max/min pooling in gemm2 registers).
// B=4, NB=8192, MB=2048, M=8192, C_IN=64, CIN=67.
// gemm1 K-permutation: features -> cols 0..63, xyz -> 64..66, pad -> 79.
// Scale 0: r=0.2, NS=16 (R=131072).  Scale 1: r=0.4, NS=32 (R=262144).
// ---------------------------------------------------------------------------

#define MTOT 8192
#define NPB  8192

__device__ float g_X0a[131072 * 128];
__device__ float g_X0b[262144 * 128];
__device__ int   g_idx0[8192 * 16];
__device__ int   g_idx1[8192 * 32];
__device__ float g_mx0[8192 * 128];
__device__ float g_mn0[8192 * 128];
__device__ float g_mx1[8192 * 128];
__device__ float g_mn1[8192 * 128];
__device__ float g_sumA[512];   // slots: 0=g1/s0, 1=g2/s0, 2=g1/s1, 3=g2/s1
__device__ float g_sqA[512];

__device__ __forceinline__ unsigned pack_h2(float lo, float hi) {
    __half2 h = __floats2half2_rn(lo, hi);
    return *(unsigned*)&h;
}

__device__ __forceinline__ void mma_f16(float* c, unsigned a0, unsigned a1,
                                        unsigned a2, unsigned a3, unsigned b0,
                                        unsigned b1) {
    asm volatile(
        "mma.sync.aligned.m16n8k16.row.col.f32.f16.f16.f32 "
        "{%0,%1,%2,%3}, {%4,%5,%6,%7}, {%8,%9}, {%0,%1,%2,%3};"
        : "+f"(c[0]), "+f"(c[1]), "+f"(c[2]), "+f"(c[3])
        : "r"(a0), "r"(a1), "r"(a2), "r"(a3), "r"(b0), "r"(b1));
}

// ---------------------------------------------------------------------------
// Merged ball query (exact fp32; folds stats zeroing + new_xyz copy).
// ---------------------------------------------------------------------------
__global__ void ballquery_merged(const float* __restrict__ xyz,
                                 const float* __restrict__ newxyz,
                                 float r2_0, float r2_1,
                                 const float* __restrict__ copySrc,
                                 float* __restrict__ copyDst, int copyN) {
    int tid = threadIdx.x;
    if (blockIdx.x == 0) {
        g_sumA[tid] = 0.0f; g_sumA[tid + 256] = 0.0f;
        g_sqA[tid]  = 0.0f; g_sqA[tid + 256]  = 0.0f;
    }
    int ct = blockIdx.x * 256 + tid;
    if (ct < copyN) copyDst[ct] = copySrc[ct];

    int gw   = (blockIdx.x * 256 + tid) >> 5;
    int lane = tid & 31;
    if (gw >= 2 * MTOT) return;
    int scl = gw >> 13;
    int q   = gw & (MTOT - 1);
    int NS  = scl ? 32 : 16;
    float r2 = scl ? r2_1 : r2_0;
    int* idx_out = (scl ? g_idx1 : g_idx0) + q * NS;

    int b = q >> 11;
    float qx = newxyz[q * 3 + 0];
    float qy = newxyz[q * 3 + 1];
    float qz = newxyz[q * 3 + 2];
    float qq = __fadd_rn(__fadd_rn(__fmul_rn(qx, qx), __fmul_rn(qy, qy)),
                         __fmul_rn(qz, qz));
    const float* P = xyz + (size_t)b * NPB * 3;
    int cnt = 0, first = -1;
    for (int start = 0; start < NPB; start += 32) {
        int i = start + lane;
        float px = P[i * 3 + 0];
        float py = P[i * 3 + 1];
        float pz = P[i * 3 + 2];
        float pp = __fadd_rn(__fadd_rn(__fmul_rn(px, px), __fmul_rn(py, py)),
                             __fmul_rn(pz, pz));
        float dt = __fadd_rn(__fadd_rn(__fmul_rn(qx, px), __fmul_rn(qy, py)),
                             __fmul_rn(qz, pz));
        float d2 = __fsub_rn(__fadd_rn(qq, pp), __fmul_rn(2.0f, dt));
        bool in = d2 < r2;
        unsigned mask = __ballot_sync(0xFFFFFFFFu, in);
        if (mask) {
            if (first < 0) first = start + (__ffs(mask) - 1);
            int pos = cnt + __popc(mask & ((1u << lane) - 1u));
            if (in && pos < NS) idx_out[pos] = i;
            cnt += __popc(mask);
            if (cnt >= NS) break;
        }
    }
    if (cnt == 0) {
        for (int j = lane; j < NS; j += 32) idx_out[j] = -1;
    } else if (cnt < NS) {
        for (int j = cnt + lane; j < NS; j += 32) idx_out[j] = first;
    }
}

// ---------------------------------------------------------------------------
// GEMM1 (fp16): X0[R,128] = gather(G)[R,80p] @ W0p^T. 512 thr, 16 warps
// (4m x 4n), warp 32x32, block 128x128, 2 row-tiles/block (W staged once).
// K-permuted layout in f16x2 words (40 words/row), pitch 44
// (44*gid ≡ 12*gid mod 32 distinct -> conflict-free frag LDS.32).
// words 0..31 = features 0..63; word 32 = (dx,dy); word 33 = (dz,0);
// words 34..39 = 0.  W0 staged with the same permutation.
// ---------------------------------------------------------------------------
#define PH1 44
#define KH1 5
#define TILES1 2
#define SMEM1H ((128 * PH1 * 2 + 256) * 4)

__global__ __launch_bounds__(512, 2) void gemm1_merged(
    const float* __restrict__ xyz, const float* __restrict__ feat,
    const float* __restrict__ newxyz, const float* __restrict__ w00,
    const float* __restrict__ w10) {
    extern __shared__ unsigned sh[];
    unsigned* As = sh;              // [128][44] f16x2 words
    unsigned* Ws = sh + 128 * PH1;  // [128][44] f16x2 words
    float* s_sum = (float*)(sh + 2 * 128 * PH1);
    float* s_sq  = s_sum + 128;
    int tid = threadIdx.x;
    int bid = blockIdx.x;
    int scl = bid >= 512;
    int lb0 = (scl ? bid - 512 : bid) * TILES1;
    int nsShift = scl ? 5 : 4;
    const int* idx = scl ? g_idx1 : g_idx0;
    const float* w0 = scl ? w10 : w00;
    float* X0 = scl ? g_X0b : g_X0a;
    float* sum_out = g_sumA + (scl ? 256 : 0);
    float* sq_out  = g_sqA + (scl ? 256 : 0);

    if (tid < 128) { s_sum[tid] = 0.0f; s_sq[tid] = 0.0f; }
    // stage W with permutation: word w<32 -> features (3+2w, 4+2w);
    // w==32 -> (c0,c1); w==33 -> (c2, 0); w>=34 -> 0
    for (int i = tid; i < 128 * 40; i += 512) {
        int o = i / 40, w = i - o * 40;
        const float* wr = w0 + o * 67;
        unsigned val;
        if (w < 32)
            val = pack_h2(wr[3 + 2 * w], wr[4 + 2 * w]);
        else if (w == 32)
            val = pack_h2(wr[0], wr[1]);
        else if (w == 33)
            val = pack_h2(wr[2], 0.0f);
        else
            val = 0u;
        Ws[o * PH1 + w] = val;
    }

    int lane = tid & 31, wid = tid >> 5;
    int wm = wid & 3, wn = wid >> 2;
    int gid = lane >> 2, t4 = lane & 3;
    const unsigned* Ab = As + (wm * 32 + gid) * PH1 + t4;
    const unsigned* Bb = Ws + (wn * 32 + gid) * PH1 + t4;

    for (int t = 0; t < TILES1; ++t) {
        if (t) __syncthreads();
        int row0 = (lb0 + t) * 128;
        {
            int r = tid >> 2, lw = tid & 3;
            int rg = row0 + r;
            int m  = rg >> nsShift;
            int p  = idx[rg];
            unsigned* grow = As + r * PH1;
            if (p < 0) {
#pragma unroll
                for (int w = lw * 10; w < lw * 10 + 10; ++w) grow[w] = 0u;
            } else {
                int gp = ((m >> 11) << 13) + p;
                const float4* frow = (const float4*)(feat + (size_t)gp * 64);
#pragma unroll
                for (int j = 0; j < 4; ++j) {
                    int f = lw + 4 * j;            // feature float4 index
                    float4 v = frow[f];
                    uint2 u;
                    u.x = pack_h2(v.x, v.y);
                    u.y = pack_h2(v.z, v.w);
                    *(uint2*)(grow + 2 * f) = u;   // words 2f, 2f+1
                }
                if (lw == 0) {
                    float dx = xyz[gp * 3 + 0] - newxyz[m * 3 + 0];
                    float dy = xyz[gp * 3 + 1] - newxyz[m * 3 + 1];
                    float dz = xyz[gp * 3 + 2] - newxyz[m * 3 + 2];
                    grow[32] = pack_h2(dx, dy);
                    grow[33] = pack_h2(dz, 0.0f);
                } else {
                    grow[32 + 2 * lw]     = 0u;    // words 34..39
                    grow[32 + 2 * lw + 1] = 0u;
                }
            }
        }
        __syncthreads();

        float acc[2][4][4];
#pragma unroll
        for (int mt = 0; mt < 2; ++mt)
#pragma unroll
            for (int nt = 0; nt < 4; ++nt)
#pragma unroll
                for (int j = 0; j < 4; ++j) acc[mt][nt][j] = 0.0f;

#pragma unroll
        for (int ks = 0; ks < KH1; ++ks) {
            int k0 = ks * 8;
            unsigned a[2][4];
#pragma unroll
            for (int mt = 0; mt < 2; ++mt) {
                const unsigned* ap = Ab + mt * 16 * PH1 + k0;
                a[mt][0] = ap[0];
                a[mt][1] = ap[8 * PH1];
                a[mt][2] = ap[4];
                a[mt][3] = ap[8 * PH1 + 4];
            }
#pragma unroll
            for (int nt = 0; nt < 4; ++nt) {
                const unsigned* bp = Bb + nt * 8 * PH1 + k0;
                unsigned b0 = bp[0], b1 = bp[4];
                mma_f16(acc[0][nt], a[0][0], a[0][1], a[0][2], a[0][3], b0,
                        b1);
                mma_f16(acc[1][nt], a[1][0], a[1][1], a[1][2], a[1][3], b0,
                        b1);
            }
        }

#pragma unroll
        for (int mt = 0; mt < 2; ++mt) {
            int rbase = row0 + wm * 32 + mt * 16 + gid;
#pragma unroll
            for (int nt = 0; nt < 4; ++nt) {
                int cc = wn * 32 + nt * 8 + t4 * 2;
                *(float2*)(X0 + (size_t)rbase * 128 + cc) =
                    make_float2(acc[mt][nt][0], acc[mt][nt][1]);
                *(float2*)(X0 + (size_t)(rbase + 8) * 128 + cc) =
                    make_float2(acc[mt][nt][2], acc[mt][nt][3]);
            }
        }
#pragma unroll
        for (int nt = 0; nt < 4; ++nt) {
#pragma unroll
            for (int j = 0; j < 2; ++j) {
                float v0 = acc[0][nt][j], v1 = acc[0][nt][j + 2];
                float v2 = acc[1][nt][j], v3 = acc[1][nt][j + 2];
                float s = v0 + v1 + v2 + v3;
                float q = v0 * v0 + v1 * v1 + v2 * v2 + v3 * v3;
#pragma unroll
                for (int o = 4; o <= 16; o <<= 1) {
                    s += __shfl_xor_sync(0xFFFFFFFFu, s, o);
                    q += __shfl_xor_sync(0xFFFFFFFFu, q, o);
                }
                if (gid == 0) {
                    int c = wn * 32 + nt * 8 + t4 * 2 + j;
                    atomicAdd(&s_sum[c], s);
                    atomicAdd(&s_sq[c], q);
                }
            }
        }
    }
    __syncthreads();
    if (tid < 128) {
        atomicAdd(&sum_out[tid], s_sum[tid]);
        atomicAdd(&sq_out[tid], s_sq[tid]);
    }
}

// ---------------------------------------------------------------------------
// GEMM2 (per-scale, fp16): 1024 threads, 32 warps (4m x 8n), warp 32x16,
// block 128x128, 2 row-tiles per block; m16n8k16 f16 MMA, fp32 accum.
// A/W in f16x2 words, 64 words/row, pitch 68. A register-prefetched.
// X1 stays in registers (max/min + stats fused). (unchanged R15)
// ---------------------------------------------------------------------------
#define PAH 68
#define KSH 8
#define TILES2 2
#define SMEM2H ((128 * PAH * 2 + 512) * 4)

template <int NS>
__global__ __launch_bounds__(1024) void gemm2_tc(
    const float* __restrict__ Xin, const float* __restrict__ w1,
    const float* __restrict__ gamma, const float* __restrict__ beta,
    float invR, const float* __restrict__ sum_in,
    const float* __restrict__ sq_in, float* __restrict__ sum_out,
    float* __restrict__ sq_out, float* __restrict__ mxp,
    float* __restrict__ mnp) {
    extern __shared__ unsigned sh[];
    unsigned* As = sh;               // [128][68] f16x2 words
    unsigned* Ws = sh + 128 * PAH;   // [128][68] f16x2 words
    float* s_sum = (float*)(sh + 2 * 128 * PAH);
    float* s_sq  = s_sum + 128;
    float* sc    = s_sq + 128;
    float* sf    = sc + 128;
    int tid = threadIdx.x;
    int lb0 = blockIdx.x * TILES2;

    float4 pf[4];
#pragma unroll
    for (int it = 0; it < 2; ++it) {
        int i = tid + it * 1024;
        int r = i >> 4, kg = i & 15;
        const float* src = Xin + (size_t)(lb0 * 128 + r) * 128 + kg * 8;
        pf[2 * it]     = *(const float4*)(src);
        pf[2 * it + 1] = *(const float4*)(src + 4);
    }

    if (tid < 128) {
        s_sum[tid] = 0.0f;
        s_sq[tid]  = 0.0f;
        float mean = sum_in[tid] * invR;
        float var  = sq_in[tid] * invR - mean * mean;
        float s    = gamma[tid] * rsqrtf(var + 1e-5f);
        sc[tid] = s;
        sf[tid] = fmaf(-mean, s, beta[tid]);
    }
    for (int i = tid; i < 128 * 16; i += 1024) {
        int o = i >> 4, kg = i & 15;
        const float* wr = w1 + o * 128 + kg * 8;
        float4 v0 = *(const float4*)(wr);
        float4 v1 = *(const float4*)(wr + 4);
        uint4 u;
        u.x = pack_h2(v0.x, v0.y);
        u.y = pack_h2(v0.z, v0.w);
        u.z = pack_h2(v1.x, v1.y);
        u.w = pack_h2(v1.z, v1.w);
        *(uint4*)(Ws + o * PAH + kg * 4) = u;
    }
    __syncthreads();

    int lane = tid & 31, wid = tid >> 5;
    int wm = wid & 3, wn = wid >> 2;
    int gid = lane >> 2, t4 = lane & 3;
    const unsigned* Ab = As + (wm * 32 + gid) * PAH + t4;
    const unsigned* Bb = Ws + (wn * 16 + gid) * PAH + t4;

    for (int t = 0; t < TILES2; ++t) {
#pragma unroll
        for (int it = 0; it < 2; ++it) {
            int i = tid + it * 1024;
            int r = i >> 4, kg = i & 15;
            int kq = kg * 8;
            float4 v0 = pf[2 * it];
            float4 v1 = pf[2 * it + 1];
            float x0 = fmaxf(fmaf(sc[kq + 0], v0.x, sf[kq + 0]), 0.0f);
            float x1 = fmaxf(fmaf(sc[kq + 1], v0.y, sf[kq + 1]), 0.0f);
            float x2 = fmaxf(fmaf(sc[kq + 2], v0.z, sf[kq + 2]), 0.0f);
            float x3 = fmaxf(fmaf(sc[kq + 3], v0.w, sf[kq + 3]), 0.0f);
            float x4 = fmaxf(fmaf(sc[kq + 4], v1.x, sf[kq + 4]), 0.0f);
            float x5 = fmaxf(fmaf(sc[kq + 5], v1.y, sf[kq + 5]), 0.0f);
            float x6 = fmaxf(fmaf(sc[kq + 6], v1.z, sf[kq + 6]), 0.0f);
            float x7 = fmaxf(fmaf(sc[kq + 7], v1.w, sf[kq + 7]), 0.0f);
            uint4 u;
            u.x = pack_h2(x0, x1);
            u.y = pack_h2(x2, x3);
            u.z = pack_h2(x4, x5);
            u.w = pack_h2(x6, x7);
            *(uint4*)(As + r * PAH + kg * 4) = u;
        }
        __syncthreads();

        if (t + 1 < TILES2) {
#pragma unroll
            for (int it = 0; it < 2; ++it) {
                int i = tid + it * 1024;
                int r = i >> 4, kg = i & 15;
                const float* src =
                    Xin + (size_t)((lb0 + t + 1) * 128 + r) * 128 + kg * 8;
                pf[2 * it]     = *(const float4*)(src);
                pf[2 * it + 1] = *(const float4*)(src + 4);
            }
        }

        float acc[2][2][4];
#pragma unroll
        for (int mt = 0; mt < 2; ++mt)
#pragma unroll
            for (int nt = 0; nt < 2; ++nt)
#pragma unroll
                for (int j = 0; j < 4; ++j) acc[mt][nt][j] = 0.0f;

#pragma unroll
        for (int ks = 0; ks < KSH; ++ks) {
            int k0 = ks * 8;
            unsigned a[2][4];
#pragma unroll
            for (int mt = 0; mt < 2; ++mt) {
                const unsigned* ap = Ab + mt * 16 * PAH + k0;
                a[mt][0] = ap[0];
                a[mt][1] = ap[8 * PAH];
                a[mt][2] = ap[4];
                a[mt][3] = ap[8 * PAH + 4];
            }
#pragma unroll
            for (int nt = 0; nt < 2; ++nt) {
                const unsigned* bp = Bb + nt * 8 * PAH + k0;
                unsigned b0 = bp[0], b1 = bp[4];
                mma_f16(acc[0][nt], a[0][0], a[0][1], a[0][2], a[0][3], b0,
                        b1);
                mma_f16(acc[1][nt], a[1][0], a[1][1], a[1][2], a[1][3], b0,
                        b1);
            }
        }

#pragma unroll
        for (int nt = 0; nt < 2; ++nt) {
#pragma unroll
            for (int j = 0; j < 2; ++j) {
                int c = wn * 16 + nt * 8 + t4 * 2 + j;
                if (NS == 16) {
#pragma unroll
                    for (int mt = 0; mt < 2; ++mt) {
                        float mx = fmaxf(acc[mt][nt][j], acc[mt][nt][j + 2]);
                        float mn = fminf(acc[mt][nt][j], acc[mt][nt][j + 2]);
#pragma unroll
                        for (int o = 4; o <= 16; o <<= 1) {
                            mx = fmaxf(mx,
                                       __shfl_xor_sync(0xFFFFFFFFu, mx, o));
                            mn = fminf(mn,
                                       __shfl_xor_sync(0xFFFFFFFFu, mn, o));
                        }
                        if (gid == 0) {
                            int mq = (lb0 + t) * 8 + wm * 2 + mt;
                            mxp[mq * 128 + c] = mx;
                            mnp[mq * 128 + c] = mn;
                        }
                    }
                } else {
                    float mx = fmaxf(fmaxf(acc[0][nt][j], acc[0][nt][j + 2]),
                                     fmaxf(acc[1][nt][j], acc[1][nt][j + 2]));
                    float mn = fminf(fminf(acc[0][nt][j], acc[0][nt][j + 2]),
                                     fminf(acc[1][nt][j], acc[1][nt][j + 2]));
#pragma unroll
                    for (int o = 4; o <= 16; o <<= 1) {
                        mx = fmaxf(mx, __shfl_xor_sync(0xFFFFFFFFu, mx, o));
                        mn = fminf(mn, __shfl_xor_sync(0xFFFFFFFFu, mn, o));
                    }
                    if (gid == 0) {
                        int mq = (lb0 + t) * 4 + wm;
                        mxp[mq * 128 + c] = mx;
                        mnp[mq * 128 + c] = mn;
                    }
                }
                float v0 = acc[0][nt][j], v1 = acc[0][nt][j + 2];
                float v2 = acc[1][nt][j], v3 = acc[1][nt][j + 2];
                float s = v0 + v1 + v2 + v3;
                float q = v0 * v0 + v1 * v1 + v2 * v2 + v3 * v3;
#pragma unroll
                for (int o = 4; o <= 16; o <<= 1) {
                    s += __shfl_xor_sync(0xFFFFFFFFu, s, o);
                    q += __shfl_xor_sync(0xFFFFFFFFu, q, o);
                }
                if (gid == 0) {
                    atomicAdd(&s_sum[c], s);
                    atomicAdd(&s_sq[c], q);
                }
            }
        }
        if (t + 1 < TILES2) __syncthreads();
    }
    __syncthreads();
    if (tid < 128) {
        atomicAdd(&sum_out[tid], s_sum[tid]);
        atomicAdd(&sq_out[tid], s_sq[tid]);
    }
}

// ---------------------------------------------------------------------------
// Final: BN finalize inline on pooled raw values; pick max/min by sign(s).
// ---------------------------------------------------------------------------
__global__ void poolout(float* __restrict__ out, const float* __restrict__ g01,
                        const float* __restrict__ b01,
                        const float* __restrict__ g11,
                        const float* __restrict__ b11, float invR0,
                        float invR1) {
    int t = blockIdx.x * blockDim.x + threadIdx.x;
    int scl = t >= MTOT * 128;
    int tt = t - scl * MTOT * 128;
    int m = tt >> 7;
    int c = tt & 127;
    const float* sum_in = g_sumA + (scl ? 384 : 128);
    const float* sq_in  = g_sqA + (scl ? 384 : 128);
    const float* gamma = scl ? g11 : g01;
    const float* beta  = scl ? b11 : b01;
    float invR = scl ? invR1 : invR0;

    float mean = sum_in[c] * invR;
    float var  = sq_in[c] * invR - mean * mean;
    float s    = gamma[c] * rsqrtf(var + 1e-5f);
    float b    = fmaf(-mean, s, beta[c]);
    float mx = (scl ? g_mx1 : g_mx0)[tt];
    float mn = (scl ? g_mn1 : g_mn0)[tt];
    float v = (s >= 0.0f) ? mx : mn;
    out[(size_t)m * 256 + (scl ? 128 : 0) + c] = fmaxf(fmaf(s, v, b), 0.0f);
}

// ---------------------------------------------------------------------------
extern "C" void kernel_launch(void* const* d_in, const int* in_sizes, int n_in,
                              void* d_out, int out_size) {
    const float* xyz  = (const float*)d_in[0];
    const float* feat = (const float*)d_in[1];
    const float* nxyz = (const float*)d_in[2];
    const float* w00 = (const float*)d_in[5];
    const float* g00 = (const float*)d_in[6];
    const float* b00 = (const float*)d_in[7];
    const float* w01 = (const float*)d_in[8];
    const float* g01 = (const float*)d_in[9];
    const float* b01 = (const float*)d_in[10];
    const float* w10 = (const float*)d_in[11];
    const float* g10 = (const float*)d_in[12];
    const float* b10 = (const float*)d_in[13];
    const float* w11 = (const float*)d_in[14];
    const float* g11 = (const float*)d_in[15];
    const float* b11 = (const float*)d_in[16];

    float* outBase = (float*)d_out;
    int featOff = out_size - MTOT * 256;
    if (featOff < 0) featOff = 0;
    float* outF = outBase + featOff;

    cudaFuncSetAttribute(gemm1_merged,
                         cudaFuncAttributeMaxDynamicSharedMemorySize, SMEM1H);
    cudaFuncSetAttribute(gemm2_tc<16>,
                         cudaFuncAttributeMaxDynamicSharedMemorySize, SMEM2H);
    cudaFuncSetAttribute(gemm2_tc<32>,
                         cudaFuncAttributeMaxDynamicSharedMemorySize, SMEM2H);

    float* X0a;
    float* X0b;
    float* sumA;
    float* sqA;
    float* mx0;
    float* mn0;
    float* mx1;
    float* mn1;
    cudaGetSymbolAddress((void**)&X0a, g_X0a);
    cudaGetSymbolAddress((void**)&X0b, g_X0b);
    cudaGetSymbolAddress((void**)&sumA, g_sumA);
    cudaGetSymbolAddress((void**)&sqA, g_sqA);
    cudaGetSymbolAddress((void**)&mx0, g_mx0);
    cudaGetSymbolAddress((void**)&mn0, g_mn0);
    cudaGetSymbolAddress((void**)&mx1, g_mx1);
    cudaGetSymbolAddress((void**)&mn1, g_mn1);

    const float r2_0 = (float)(0.2 * 0.2);
    const float r2_1 = (float)(0.4 * 0.4);
    const float invR0 = 1.0f / 131072.0f;
    const float invR1 = 1.0f / 262144.0f;

    ballquery_merged<<<2048, 256>>>(xyz, nxyz, r2_0, r2_1, nxyz, outBase,
                                    featOff);
    gemm1_merged<<<1536, 512, SMEM1H>>>(xyz, feat, nxyz, w00, w10);
    // scale 1 first: gemm1's last-written X0b tail is still L2-resident
    gemm2_tc<32><<<1024, 1024, SMEM2H>>>(X0b, w11, g10, b10, invR1,
                                         sumA + 256, sqA + 256, sumA + 384,
                                         sqA + 384, mx1, mn1);
    gemm2_tc<16><<<512, 1024, SMEM2H>>>(X0a, w01, g00, b00, invR0, sumA + 0,
                                        sqA + 0, sumA + 128, sqA + 128, mx0,
                                        mn0);
    poolout<<<2 * MTOT * 128 / 256, 256>>>(outF, g01, b01, g11, b11, invR0,
                                           invR1);
}